// round 12
// baseline (speedup 1.0000x reference)
#include <cuda_runtime.h>
#include <cstdint>

#define Nn  50000
#define NTt 300000
#define RPk 16
#define Ee  32
#define Cc  32

// ------------------------- device scratch (static, no allocs) -------------
__device__ float g_lat1[(size_t)NTt * RPk];        // 19.2 MB
__device__ float g_lat2[(size_t)NTt * RPk];        // 19.2 MB
__device__ float g_colsum[Nn * RPk];               // 3.2 MB
__device__ float g_rowsum[Nn * RPk];               // 3.2 MB
__device__ float g_h[Nn * Ee];                     // 6.4 MB
__device__ float g_h2[(size_t)RPk * Nn * Ee];      // 102.4 MB
__device__ int   g_deg_s[Nn];
__device__ int   g_deg_o[Nn];
__device__ int   g_off_s[Nn];
__device__ int   g_off_o[Nn];
__device__ int   g_cur_s[Nn];
__device__ int   g_cur_o[Nn];
__device__ int   g_perm_s[NTt];
__device__ int   g_perm_o[NTt];
__device__ int   g_counter[2];

// ------------------------- small helpers ----------------------------------
typedef unsigned long long ULL;
union F4U { float4 f; ULL u[2]; float s[4]; };

__device__ __forceinline__ ULL splat2(float v) {
    ULL r;
    asm("mov.b64 %0, {%1, %1};" : "=l"(r) : "f"(v));
    return r;
}
__device__ __forceinline__ ULL ffma2(ULL a, ULL b, ULL c) {
    ULL d;
    asm("fma.rn.f32x2 %0, %1, %2, %3;" : "=l"(d) : "l"(a), "l"(b), "l"(c));
    return d;
}
__device__ __forceinline__ void red4(float4* a, float4 v) {
    asm volatile("red.global.add.v4.f32 [%0], {%1, %2, %3, %4};"
                 :: "l"(a), "f"(v.x), "f"(v.y), "f"(v.z), "f"(v.w) : "memory");
}
__device__ __forceinline__ void red1(float* a, float v) {
    asm volatile("red.global.add.f32 [%0], %1;" :: "l"(a), "f"(v) : "memory");
}
// f32 -> tf32 (bits in a b32 reg)
__device__ __forceinline__ unsigned f2t(float f) {
    unsigned r;
    asm("cvt.rna.tf32.f32 %0, %1;" : "=r"(r) : "f"(f));
    return r;
}
// D(16x8,f32) += A(16x8,tf32,row) * B(8x8,tf32,col)
__device__ __forceinline__ void mma8(float* d, unsigned a0, unsigned a1,
                                     unsigned a2, unsigned a3,
                                     unsigned b0, unsigned b1) {
    asm("mma.sync.aligned.m16n8k8.row.col.f32.tf32.tf32.f32 "
        "{%0,%1,%2,%3}, {%4,%5,%6,%7}, {%8,%9}, {%0,%1,%2,%3};"
        : "+f"(d[0]), "+f"(d[1]), "+f"(d[2]), "+f"(d[3])
        : "r"(a0), "r"(a1), "r"(a2), "r"(a3), "r"(b0), "r"(b1));
}

// ------------------------- init: zero scratch -----------------------------
__global__ void k_init() {
    size_t i = (size_t)blockIdx.x * blockDim.x + threadIdx.x;
    size_t stride = (size_t)gridDim.x * blockDim.x;
    float4 z = make_float4(0.f, 0.f, 0.f, 0.f);
    for (size_t p = i; p < (size_t)RPk * Nn * Ee / 4; p += stride)
        ((float4*)g_h2)[p] = z;
    for (size_t p = i; p < (size_t)Nn * RPk / 4; p += stride) {
        ((float4*)g_colsum)[p] = z;
        ((float4*)g_rowsum)[p] = z;
    }
    for (size_t p = i; p < (size_t)Nn * Ee / 4; p += stride)
        ((float4*)g_h)[p] = z;
    for (size_t p = i; p < Nn / 4; p += stride) {
        ((int4*)g_deg_s)[p] = make_int4(0, 0, 0, 0);
        ((int4*)g_deg_o)[p] = make_int4(0, 0, 0, 0);
    }
    if (i == 0) { g_counter[0] = 0; g_counter[1] = 0; }
}

// ------------------------- degree count -----------------------------------
__global__ void k_deg(const int* __restrict__ s_idx, const int* __restrict__ o_idx) {
    int t = blockIdx.x * blockDim.x + threadIdx.x;
    if (t < NTt) {
        atomicAdd(&g_deg_s[s_idx[t]], 1);
        atomicAdd(&g_deg_o[o_idx[t]], 1);
    }
}

// ---------------- CSR range allocation (warp-aggregated, unordered) -------
__global__ void k_alloc() {
    int i = blockIdx.x * blockDim.x + threadIdx.x;
    int lane = threadIdx.x & 31;
    int ds = (i < Nn) ? g_deg_s[i] : 0;
    int dq = (i < Nn) ? g_deg_o[i] : 0;
    int ss = ds, so = dq;
#pragma unroll
    for (int off = 1; off < 32; off <<= 1) {
        int a = __shfl_up_sync(0xffffffffu, ss, off);
        int b = __shfl_up_sync(0xffffffffu, so, off);
        if (lane >= off) { ss += a; so += b; }
    }
    int bs = 0, bo = 0;
    if (lane == 31) {
        bs = atomicAdd(&g_counter[0], ss);
        bo = atomicAdd(&g_counter[1], so);
    }
    bs = __shfl_sync(0xffffffffu, bs, 31);
    bo = __shfl_sync(0xffffffffu, bo, 31);
    if (i < Nn) {
        int es = bs + ss - ds;
        int eo = bo + so - dq;
        g_off_s[i] = es; g_cur_s[i] = es;
        g_off_o[i] = eo; g_cur_o[i] = eo;
    }
}

// --------- fused double-MLP (tf32 tensor cores) + softmax + seg sums ------
// block = 128 edges, 256 threads (8 warps, warp = 16-edge m-stripe).
// smem (32-bit words), 26840 = 107.4 KB -> 2 blocks/SM:
//   X   [128][68] tf32 @ 0      (8704)
//   H   [128][68] tf32 @ 8704   (8704)  -- reused as lat[128][17] f32
//   Wa  transposed [64][8g*12+n] @ 17408 (6144)   Ws[k*96 + g*12 + n]
//   Wb  transposed @ 23552 (3200)                 Wbs[k*50 + g*6 + n]
//   ba [64] @ 26752 ; bb [16] @ 26816 ; red [8] @ 26832
#define SM_X    0
#define SM_H    8704
#define SM_W    17408
#define SM_WB   23552
#define SM_BA   26752
#define SM_BB   26816
#define SM_RED  26832
#define SM_FLOATS 26840

__device__ __forceinline__ void softmax16(float* l) {
    float m = l[0];
#pragma unroll
    for (int k = 1; k < 16; k++) m = fmaxf(m, l[k]);
    float s = 0.f;
#pragma unroll
    for (int k = 0; k < 16; k++) { l[k] = __expf(l[k] - m); s += l[k]; }
    float inv = 1.f / s;
#pragma unroll
    for (int k = 0; k < 16; k++) l[k] *= inv;
}

__device__ __forceinline__ void stage_w(float* sm, int tid,
                                        const float* __restrict__ Wa,
                                        const float* __restrict__ ba,
                                        const float* __restrict__ Wb,
                                        const float* __restrict__ bb) {
    unsigned* Ws  = (unsigned*)(sm + SM_W);
    unsigned* Wbs = (unsigned*)(sm + SM_WB);
    for (int i = tid; i < 4096; i += 256) {
        int k = i >> 6, c = i & 63;          // c = n*8 + g
        int n = c >> 3, g = c & 7;
        Ws[k * 96 + g * 12 + n] = f2t(Wa[i]);
    }
    for (int i = tid; i < 1024; i += 256) {
        int k = i >> 4, c = i & 15;
        int n = c >> 3, g = c & 7;
        Wbs[k * 50 + g * 6 + n] = f2t(Wb[i]);
    }
    if (tid < 64) sm[SM_BA + tid] = ba[tid];
    if (tid < 16) sm[SM_BB + tid] = bb[tid];
}

__device__ __forceinline__ void mlp_layer(float* sm, int tid, int e_base,
                                          const int* __restrict__ nidx,
                                          float* __restrict__ lat_out,
                                          float* __restrict__ sum_out) {
    int lane = tid & 31, warp = tid >> 5;
    int g = lane >> 2, t4 = lane & 3;
    int m0 = warp * 16;
    const unsigned* Xs  = (const unsigned*)(sm + SM_X);
    const unsigned* Ws  = (const unsigned*)(sm + SM_W);
    const unsigned* Wbs = (const unsigned*)(sm + SM_WB);
    unsigned* Hs = (unsigned*)(sm + SM_H);

    // ---- phase 1: H[128][64] = relu(X @ Wa + ba) via m16n8k8 tf32 ----
    {
        float dacc[8][4];
#pragma unroll
        for (int n = 0; n < 8; n++) {
            float blo = sm[SM_BA + n * 8 + 2 * t4];
            float bhi = sm[SM_BA + n * 8 + 2 * t4 + 1];
            dacc[n][0] = blo; dacc[n][1] = bhi;
            dacc[n][2] = blo; dacc[n][3] = bhi;
        }
#pragma unroll
        for (int k8 = 0; k8 < 8; k8++) {
            int kb = k8 * 8;
            unsigned a0 = Xs[(m0 + g) * 68 + kb + t4];
            unsigned a1 = Xs[(m0 + g + 8) * 68 + kb + t4];
            unsigned a2 = Xs[(m0 + g) * 68 + kb + t4 + 4];
            unsigned a3 = Xs[(m0 + g + 8) * 68 + kb + t4 + 4];
            // B-frags for all 8 n-blocks: 4x LDS.128 (transposed layout)
            const unsigned* wlo = &Ws[(kb + t4) * 96 + g * 12];
            const unsigned* whi = &Ws[(kb + t4 + 4) * 96 + g * 12];
            uint4 bl0 = *(const uint4*)wlo;
            uint4 bl1 = *(const uint4*)(wlo + 4);
            uint4 bh0 = *(const uint4*)whi;
            uint4 bh1 = *(const uint4*)(whi + 4);
            unsigned blo[8] = { bl0.x, bl0.y, bl0.z, bl0.w, bl1.x, bl1.y, bl1.z, bl1.w };
            unsigned bhi[8] = { bh0.x, bh0.y, bh0.z, bh0.w, bh1.x, bh1.y, bh1.z, bh1.w };
#pragma unroll
            for (int n = 0; n < 8; n++)
                mma8(dacc[n], a0, a1, a2, a3, blo[n], bhi[n]);
        }
        // relu + cvt to tf32 + store H
#pragma unroll
        for (int n = 0; n < 8; n++) {
            unsigned lo0 = f2t(fmaxf(dacc[n][0], 0.f));
            unsigned lo1 = f2t(fmaxf(dacc[n][1], 0.f));
            unsigned hi0 = f2t(fmaxf(dacc[n][2], 0.f));
            unsigned hi1 = f2t(fmaxf(dacc[n][3], 0.f));
            ULL p0 = (ULL)lo0 | ((ULL)lo1 << 32);
            ULL p1 = (ULL)hi0 | ((ULL)hi1 << 32);
            *(ULL*)&Hs[(m0 + g) * 68 + n * 8 + 2 * t4] = p0;
            *(ULL*)&Hs[(m0 + g + 8) * 68 + n * 8 + 2 * t4] = p1;
        }
    }
    __syncthreads();

    // ---- phase 2: lat[128][16] = H @ Wb + bb ----
    float facc[2][4];
    {
#pragma unroll
        for (int n = 0; n < 2; n++) {
            float blo = sm[SM_BB + n * 8 + 2 * t4];
            float bhi = sm[SM_BB + n * 8 + 2 * t4 + 1];
            facc[n][0] = blo; facc[n][1] = bhi;
            facc[n][2] = blo; facc[n][3] = bhi;
        }
#pragma unroll
        for (int k8 = 0; k8 < 8; k8++) {
            int kb = k8 * 8;
            unsigned a0 = Hs[(m0 + g) * 68 + kb + t4];
            unsigned a1 = Hs[(m0 + g + 8) * 68 + kb + t4];
            unsigned a2 = Hs[(m0 + g) * 68 + kb + t4 + 4];
            unsigned a3 = Hs[(m0 + g + 8) * 68 + kb + t4 + 4];
            uint2 wl = *(const uint2*)&Wbs[(kb + t4) * 50 + g * 6];
            uint2 wh = *(const uint2*)&Wbs[(kb + t4 + 4) * 50 + g * 6];
            mma8(facc[0], a0, a1, a2, a3, wl.x, wh.x);
            mma8(facc[1], a0, a1, a2, a3, wl.y, wh.y);
        }
    }
    __syncthreads();   // all H reads done before lat overlays H region
    float* latF = sm + SM_H;
#pragma unroll
    for (int n = 0; n < 2; n++) {
        latF[(m0 + g) * 17 + n * 8 + 2 * t4]         = facc[n][0];
        latF[(m0 + g) * 17 + n * 8 + 2 * t4 + 1]     = facc[n][1];
        latF[(m0 + g + 8) * 17 + n * 8 + 2 * t4]     = facc[n][2];
        latF[(m0 + g + 8) * 17 + n * 8 + 2 * t4 + 1] = facc[n][3];
    }
    __syncthreads();

    // ---- epilogue: softmax, emit latents, segment-sum atomics ----
    float part = 0.f;
    if (tid < 128 && e_base + tid < NTt) {
        int e = e_base + tid;
        float l[16];
        const float* lr = sm + SM_H + tid * 17;
#pragma unroll
        for (int c = 0; c < 16; c++) l[c] = lr[c];
        softmax16(l);
        float4* po = (float4*)(lat_out + (size_t)e * 16);
#pragma unroll
        for (int q = 0; q < 4; q++)
            po[q] = make_float4(l[4 * q], l[4 * q + 1], l[4 * q + 2], l[4 * q + 3]);
        int ix = nidx[e];
#pragma unroll
        for (int k = 1; k < 16; k++)
            red1(&sum_out[ix * k], l[k]);
        part = l[0];
    }
#pragma unroll
    for (int off = 16; off; off >>= 1)
        part += __shfl_down_sync(0xffffffffu, part, off);
    if ((tid & 31) == 0) sm[SM_RED + (tid >> 5)] = part;
    __syncthreads();
    if (tid == 0) {
        float a = 0.f;
#pragma unroll
        for (int i = 0; i < 8; i++) a += sm[SM_RED + i];
        red1(&sum_out[0], a);
    }
    __syncthreads();   // lat region (H) free before next layer writes H
}

__global__ void __launch_bounds__(256)
k_mlp(const int* __restrict__ s_idx, const int* __restrict__ o_idx,
      const float* __restrict__ nhots,
      const float* __restrict__ W1a, const float* __restrict__ b1a,
      const float* __restrict__ W1b, const float* __restrict__ b1b,
      const float* __restrict__ W2a, const float* __restrict__ b2a,
      const float* __restrict__ W2b, const float* __restrict__ b2b,
      float* __restrict__ lat1, float* __restrict__ lat2,
      float* __restrict__ colsum, float* __restrict__ rowsum) {
    extern __shared__ __align__(16) float sm[];
    int tid = threadIdx.x;
    int e_base = blockIdx.x * 128;

    // ---- stage X [128 edges][64] as tf32, row pad 68 (17 uint4) ----
    unsigned* Xs = (unsigned*)(sm + SM_X);
#pragma unroll
    for (int j = 0; j < 8; j++) {
        int idx4 = tid + 256 * j;            // 0..2047 float4 slots
        int e = idx4 >> 4, kq = idx4 & 15;
        float4 v = make_float4(0.f, 0.f, 0.f, 0.f);
        if (e_base + e < NTt)
            v = __ldg((const float4*)(nhots + (size_t)(e_base + e) * 64) + kq);
        uint4 t;
        t.x = f2t(v.x); t.y = f2t(v.y); t.z = f2t(v.z); t.w = f2t(v.w);
        *(uint4*)&Xs[e * 68 + kq * 4] = t;
    }
    stage_w(sm, tid, W1a, b1a, W1b, b1b);
    __syncthreads();

    mlp_layer(sm, tid, e_base, o_idx, lat1, colsum);

    stage_w(sm, tid, W2a, b2a, W2b, b2b);
    __syncthreads();

    mlp_layer(sm, tid, e_base, s_idx, lat2, rowsum);
}

__global__ void k_scatter(const int* __restrict__ s_idx,
                          const int* __restrict__ o_idx) {
    int t = blockIdx.x * blockDim.x + threadIdx.x;
    if (t < NTt) {
        int s = s_idx[t], o = o_idx[t];
        g_perm_s[atomicAdd(&g_cur_s[s], 1)] = t;
        g_perm_o[atomicAdd(&g_cur_o[o], 1)] = t;
    }
}

// ------ layer-1 spmm, warp per o: weights loaded once, red into h[s] ------
__global__ void __launch_bounds__(256)
k_spmm1(const int* __restrict__ s_idx, const float* __restrict__ w1) {
    int w = (blockIdx.x * blockDim.x + threadIdx.x) >> 5;
    int lane = threadIdx.x & 31;
    if (w >= Nn) return;
    int o = w;
    int deg = g_deg_o[o];
    if (deg == 0) return;
    int beg = g_off_o[o], end = beg + deg;

    float wk[16];
#pragma unroll
    for (int k = 0; k < 16; k++) {
        int j = o * k;
        float c = g_colsum[j];
        float inv = (c > 0.f) ? __frcp_rn(c) : 0.f;
        wk[k] = w1[(size_t)j * 32 + lane] * inv;
    }

    int tA = __ldg(&g_perm_o[beg]);
    int tB = (beg + 1 < end) ? __ldg(&g_perm_o[beg + 1]) : tA;
    int s = __ldg(&s_idx[tA]);
    float lv = (lane < 16) ? __ldg(&g_lat1[(size_t)tA * 16 + lane]) : 0.f;
    for (int p = beg; p < end; p++) {
        int tC = (p + 2 < end) ? __ldg(&g_perm_o[p + 2]) : tB;
        int s_n = s; float lv_n = lv;
        if (p + 1 < end) {
            s_n = __ldg(&s_idx[tB]);
            lv_n = (lane < 16) ? __ldg(&g_lat1[(size_t)tB * 16 + lane]) : 0.f;
        }
        float acc = 0.f;
#pragma unroll
        for (int k = 0; k < 16; k++)
            acc += __shfl_sync(0xffffffffu, lv, k) * wk[k];
        red1(&g_h[s * 32 + lane], acc);
        s = s_n; lv = lv_n; tB = tC;
    }
}

// ------------------------- h = relu(h + bias1) -----------------------------
__global__ void k_relu(const float* __restrict__ bias1) {
    int i = blockIdx.x * blockDim.x + threadIdx.x;
    if (i < Nn * Ee)
        g_h[i] = fmaxf(g_h[i] + bias1[i & 31], 0.f);
}

// -------- h2 row j=0 (k=0 bin): block-aggregated global reduction ---------
__global__ void __launch_bounds__(256)
k_h2k0(const int* __restrict__ o_idx) {
    __shared__ float sacc[8][32];
    int lane = threadIdx.x & 31, wid = threadIdx.x >> 5;
    int gw = blockIdx.x * 8 + wid;
    int nw = gridDim.x * 8;
    float acc = 0.f;
    for (int t = gw; t < NTt; t += nw) {
        float l0 = __ldg(&g_lat2[(size_t)t * 16]);
        int o = __ldg(&o_idx[t]);
        acc += l0 * g_h[o * 32 + lane];
    }
    sacc[wid][lane] = acc;
    __syncthreads();
    if (wid == 0) {
        float tot = 0.f;
#pragma unroll
        for (int i = 0; i < 8; i++) tot += sacc[i][lane];
        red1(&g_h2[lane], tot);
    }
}

// --------------- layer-2 spmm into h2 (warp per s, k>=1 only) -------------
__global__ void __launch_bounds__(256)
k_spmm2(const int* __restrict__ o_idx) {
    __shared__ __align__(16) float stage[8][16 * 32];
    int wid = threadIdx.x >> 5, lane = threadIdx.x & 31;
    int s = blockIdx.x * 8 + wid;
    if (s >= Nn) return;
    int deg = g_deg_s[s];
    if (deg == 0) return;
    int beg = g_off_s[s], end = beg + deg;
    float acc[16];
#pragma unroll
    for (int k = 0; k < 16; k++) acc[k] = 0.f;

    int tA = __ldg(&g_perm_s[beg]);
    int tB = (beg + 1 < end) ? __ldg(&g_perm_s[beg + 1]) : tA;
    int o = __ldg(&o_idx[tA]);
    float lv = (lane < 16) ? __ldg(&g_lat2[(size_t)tA * 16 + lane]) : 0.f;
    for (int p = beg; p < end; p++) {
        int tC = (p + 2 < end) ? __ldg(&g_perm_s[p + 2]) : tB;
        int o_n = o; float lv_n = lv;
        if (p + 1 < end) {
            o_n = __ldg(&o_idx[tB]);
            lv_n = (lane < 16) ? __ldg(&g_lat2[(size_t)tB * 16 + lane]) : 0.f;
        }
        float hv = g_h[o * 32 + lane];
#pragma unroll
        for (int k = 1; k < 16; k++)
            acc[k] += __shfl_sync(0xffffffffu, lv, k) * hv;
        o = o_n; lv = lv_n; tB = tC;
    }
    float* st = stage[wid];
#pragma unroll
    for (int k = 1; k < 16; k++) st[k * 32 + lane] = acc[k];
    __syncwarp();
#pragma unroll
    for (int it = 0; it < 4; it++) {
        int idx = it * 32 + lane;        // 0..127 over 16 rows x 8 float4
        if (idx >= 8) {                  // skip k=0 (handled by k_h2k0)
            int k = idx >> 3, q = idx & 7;
            float4 v = ((float4*)st)[idx];
            int j = s * k;
            red4(&((float4*)g_h2)[(size_t)j * 8 + q], v);
        }
    }
}

// ------------------- einsum + bias2: out, 2 nodes / thread ----------------
__global__ void __launch_bounds__(256)
k_out(const float* __restrict__ w2, const float* __restrict__ bias2,
      float* __restrict__ out) {
    extern __shared__ __align__(16) float sw2[];   // 16*32*32 floats = 64 KB
    for (int i = threadIdx.x; i < 16 * 32 * 32; i += 256) sw2[i] = w2[i];
    __syncthreads();
    int n0 = blockIdx.x * 256 + threadIdx.x;       // 0..24999
    if (n0 >= Nn / 2) return;
    int n1 = n0 + Nn / 2;
    ULL accA[16], accB[16];
#pragma unroll
    for (int c2 = 0; c2 < 16; c2++) {
        accA[c2] = ((const ULL*)bias2)[c2];
        accB[c2] = accA[c2];
    }
#pragma unroll 1
    for (int r = 0; r < 16; r++) {
        int jA = r * Nn + n0;
        int jB = jA + Nn / 2;
        float ra = g_rowsum[jA], rb = g_rowsum[jB];
        float invA = (ra > 0.f) ? __frcp_rn(ra) : 0.f;
        float invB = (rb > 0.f) ? __frcp_rn(rb) : 0.f;
        const float4* hA = (const float4*)&g_h2[(size_t)jA * 32];
        const float4* hB = (const float4*)&g_h2[(size_t)jB * 32];
#pragma unroll
        for (int e4 = 0; e4 < 8; e4++) {
            float4 va = hA[e4];
            float4 vb = hB[e4];
            float xa[4] = { va.x * invA, va.y * invA, va.z * invA, va.w * invA };
            float xb[4] = { vb.x * invB, vb.y * invB, vb.z * invB, vb.w * invB };
#pragma unroll
            for (int u = 0; u < 4; u++) {
                int e = e4 * 4 + u;
                ULL sa = splat2(xa[u]);
                ULL sb = splat2(xb[u]);
                const float4* wr4 = (const float4*)&sw2[(r * 32 + e) * 32];
#pragma unroll
                for (int c4 = 0; c4 < 8; c4++) {
                    F4U w; w.f = wr4[c4];
                    accA[2 * c4]     = ffma2(sa, w.u[0], accA[2 * c4]);
                    accA[2 * c4 + 1] = ffma2(sa, w.u[1], accA[2 * c4 + 1]);
                    accB[2 * c4]     = ffma2(sb, w.u[0], accB[2 * c4]);
                    accB[2 * c4 + 1] = ffma2(sb, w.u[1], accB[2 * c4 + 1]);
                }
            }
        }
    }
    ULL* opA = (ULL*)(out + (size_t)n0 * 32);
    ULL* opB = (ULL*)(out + (size_t)n1 * 32);
#pragma unroll
    for (int c2 = 0; c2 < 16; c2++) { opA[c2] = accA[c2]; opB[c2] = accB[c2]; }
}

// ------------------------- launch -----------------------------------------
extern "C" void kernel_launch(void* const* d_in, const int* in_sizes, int n_in,
                              void* d_out, int out_size) {
    const int*   s_idx = (const int*)d_in[0];
    const int*   o_idx = (const int*)d_in[1];
    const float* nhots = (const float*)d_in[2];
    const float* W1a   = (const float*)d_in[3];
    const float* b1a   = (const float*)d_in[4];
    const float* W1b   = (const float*)d_in[5];
    const float* b1b   = (const float*)d_in[6];
    const float* W2a   = (const float*)d_in[7];
    const float* b2a   = (const float*)d_in[8];
    const float* W2b   = (const float*)d_in[9];
    const float* b2b   = (const float*)d_in[10];
    const float* w1    = (const float*)d_in[11];
    const float* w2    = (const float*)d_in[12];
    const float* bias1 = (const float*)d_in[13];
    const float* bias2 = (const float*)d_in[14];
    float* out = (float*)d_out;

    static float* lat1p = nullptr;
    static float* lat2p = nullptr;
    static float* colp = nullptr;
    static float* rowp = nullptr;
    if (!lat1p) {
        cudaGetSymbolAddress((void**)&lat1p, g_lat1);
        cudaGetSymbolAddress((void**)&lat2p, g_lat2);
        cudaGetSymbolAddress((void**)&colp, g_colsum);
        cudaGetSymbolAddress((void**)&rowp, g_rowsum);
        cudaFuncSetAttribute(k_mlp, cudaFuncAttributeMaxDynamicSharedMemorySize,
                             SM_FLOATS * (int)sizeof(float));
        cudaFuncSetAttribute(k_out, cudaFuncAttributeMaxDynamicSharedMemorySize,
                             16 * 32 * 32 * (int)sizeof(float));
    }

    int mlp_blocks = (NTt + 127) / 128;
    size_t mlp_smem = SM_FLOATS * sizeof(float);

    k_init<<<2048, 256>>>();                                   // 0
    k_deg<<<(NTt + 255) / 256, 256>>>(s_idx, o_idx);           // 1
    k_alloc<<<(Nn + 255) / 256, 256>>>();                      // 2
    k_mlp<<<mlp_blocks, 256, mlp_smem>>>(s_idx, o_idx, nhots,  // 3 <- ncu slot
                                         W1a, b1a, W1b, b1b,
                                         W2a, b2a, W2b, b2b,
                                         lat1p, lat2p, colp, rowp);
    k_scatter<<<(NTt + 255) / 256, 256>>>(s_idx, o_idx);       // 4
    k_spmm1<<<(Nn * 32 + 255) / 256, 256>>>(s_idx, w1);        // 5
    k_relu<<<(Nn * Ee + 255) / 256, 256>>>(bias1);             // 6
    k_h2k0<<<512, 256>>>(o_idx);                               // 7
    k_spmm2<<<(Nn + 7) / 8, 256>>>(o_idx);                     // 8
    k_out<<<(Nn / 2 + 255) / 256, 256, 16 * 32 * 32 * (int)sizeof(float)>>>(w2, bias2, out); // 9
}

// round 13
// speedup vs baseline: 1.2182x; 1.2182x over previous
#include <cuda_runtime.h>
#include <cstdint>

#define Nn  50000
#define NTt 300000
#define RPk 16
#define Ee  32
#define Cc  32

// ------------------------- device scratch (static, no allocs) -------------
__device__ float g_lat1[(size_t)NTt * RPk];        // 19.2 MB
__device__ float g_lat2[(size_t)NTt * RPk];        // 19.2 MB
__device__ float g_colsum[Nn * RPk];               // 3.2 MB
__device__ float g_rowsum[Nn * RPk];               // 3.2 MB
__device__ float g_h[Nn * Ee];                     // 6.4 MB
__device__ float g_h2[(size_t)RPk * Nn * Ee];      // 102.4 MB
__device__ int   g_deg_s[Nn];
__device__ int   g_deg_o[Nn];
__device__ int   g_off_s[Nn];
__device__ int   g_off_o[Nn];
__device__ int   g_cur_s[Nn];
__device__ int   g_cur_o[Nn];
__device__ int   g_perm_s[NTt];
__device__ int   g_perm_o[NTt];
__device__ int   g_counter[2];

// ------------------------- small helpers ----------------------------------
typedef unsigned long long ULL;
union F4U { float4 f; ULL u[2]; float s[4]; };

__device__ __forceinline__ ULL splat2(float v) {
    ULL r;
    asm("mov.b64 %0, {%1, %1};" : "=l"(r) : "f"(v));
    return r;
}
__device__ __forceinline__ ULL ffma2(ULL a, ULL b, ULL c) {
    ULL d;
    asm("fma.rn.f32x2 %0, %1, %2, %3;" : "=l"(d) : "l"(a), "l"(b), "l"(c));
    return d;
}
__device__ __forceinline__ void red4(float4* a, float4 v) {
    asm volatile("red.global.add.v4.f32 [%0], {%1, %2, %3, %4};"
                 :: "l"(a), "f"(v.x), "f"(v.y), "f"(v.z), "f"(v.w) : "memory");
}
__device__ __forceinline__ void red1(float* a, float v) {
    asm volatile("red.global.add.f32 [%0], %1;" :: "l"(a), "f"(v) : "memory");
}
// f32 -> tf32 (bits in a b32 reg)
__device__ __forceinline__ unsigned f2t(float f) {
    unsigned r;
    asm("cvt.rna.tf32.f32 %0, %1;" : "=r"(r) : "f"(f));
    return r;
}
// D(16x8,f32) += A(16x8,tf32,row) * B(8x8,tf32,col)
__device__ __forceinline__ void mma8(float* d, unsigned a0, unsigned a1,
                                     unsigned a2, unsigned a3,
                                     unsigned b0, unsigned b1) {
    asm("mma.sync.aligned.m16n8k8.row.col.f32.tf32.tf32.f32 "
        "{%0,%1,%2,%3}, {%4,%5,%6,%7}, {%8,%9}, {%0,%1,%2,%3};"
        : "+f"(d[0]), "+f"(d[1]), "+f"(d[2]), "+f"(d[3])
        : "r"(a0), "r"(a1), "r"(a2), "r"(a3), "r"(b0), "r"(b1));
}

// ------------------- init (small): everything except h2 -------------------
__global__ void k_init_small() {
    size_t i = (size_t)blockIdx.x * blockDim.x + threadIdx.x;
    size_t stride = (size_t)gridDim.x * blockDim.x;
    float4 z = make_float4(0.f, 0.f, 0.f, 0.f);
    for (size_t p = i; p < (size_t)Nn * RPk / 4; p += stride) {
        ((float4*)g_colsum)[p] = z;
        ((float4*)g_rowsum)[p] = z;
    }
    for (size_t p = i; p < (size_t)Nn * Ee / 4; p += stride)
        ((float4*)g_h)[p] = z;
    for (size_t p = i; p < Nn / 4; p += stride) {
        ((int4*)g_deg_s)[p] = make_int4(0, 0, 0, 0);
        ((int4*)g_deg_o)[p] = make_int4(0, 0, 0, 0);
    }
    if (i == 0) { g_counter[0] = 0; g_counter[1] = 0; }
}

// ------------------- init (big): zero h2 (102.4 MB) -----------------------
__global__ void k_init_h2() {
    size_t i = (size_t)blockIdx.x * blockDim.x + threadIdx.x;
    size_t stride = (size_t)gridDim.x * blockDim.x;
    float4 z = make_float4(0.f, 0.f, 0.f, 0.f);
    for (size_t p = i; p < (size_t)RPk * Nn * Ee / 4; p += stride)
        ((float4*)g_h2)[p] = z;
}

// ------------------------- degree count -----------------------------------
__global__ void k_deg(const int* __restrict__ s_idx, const int* __restrict__ o_idx) {
    int t = blockIdx.x * blockDim.x + threadIdx.x;
    if (t < NTt) {
        atomicAdd(&g_deg_s[s_idx[t]], 1);
        atomicAdd(&g_deg_o[o_idx[t]], 1);
    }
}

// ---------------- CSR range allocation (warp-aggregated, unordered) -------
__global__ void k_alloc() {
    int i = blockIdx.x * blockDim.x + threadIdx.x;
    int lane = threadIdx.x & 31;
    int ds = (i < Nn) ? g_deg_s[i] : 0;
    int dq = (i < Nn) ? g_deg_o[i] : 0;
    int ss = ds, so = dq;
#pragma unroll
    for (int off = 1; off < 32; off <<= 1) {
        int a = __shfl_up_sync(0xffffffffu, ss, off);
        int b = __shfl_up_sync(0xffffffffu, so, off);
        if (lane >= off) { ss += a; so += b; }
    }
    int bs = 0, bo = 0;
    if (lane == 31) {
        bs = atomicAdd(&g_counter[0], ss);
        bo = atomicAdd(&g_counter[1], so);
    }
    bs = __shfl_sync(0xffffffffu, bs, 31);
    bo = __shfl_sync(0xffffffffu, bo, 31);
    if (i < Nn) {
        int es = bs + ss - ds;
        int eo = bo + so - dq;
        g_off_s[i] = es; g_cur_s[i] = es;
        g_off_o[i] = eo; g_cur_o[i] = eo;
    }
}

// --------- fused double-MLP (tf32 tensor cores) + softmax + seg sums ------
// block = 128 edges, 256 threads (8 warps, warp = 16-edge m-stripe).
// smem (32-bit words):
//   X  [128][68] tf32 @ 0      (8704)
//   H  [128][68] tf32 @ 8704   (8704)  -- reused as lat[128][17] f32
//   Wa [64][72]  tf32 @ 17408  (4608)  -- re-staged per layer
//   Wb [64][24]  tf32 @ 22016  (1536)
//   ba [64] f32 @ 23552 ; bb [16] f32 @ 23616 ; red [8] @ 23632
#define SM_X    0
#define SM_H    8704
#define SM_W    17408
#define SM_WB   22016
#define SM_BA   23552
#define SM_BB   23616
#define SM_RED  23632
#define SM_FLOATS 23640

__device__ __forceinline__ void softmax16(float* l) {
    float m = l[0];
#pragma unroll
    for (int k = 1; k < 16; k++) m = fmaxf(m, l[k]);
    float s = 0.f;
#pragma unroll
    for (int k = 0; k < 16; k++) { l[k] = __expf(l[k] - m); s += l[k]; }
    float inv = 1.f / s;
#pragma unroll
    for (int k = 0; k < 16; k++) l[k] *= inv;
}

__device__ __forceinline__ void stage_w(float* sm, int tid,
                                        const float* __restrict__ Wa,
                                        const float* __restrict__ ba,
                                        const float* __restrict__ Wb,
                                        const float* __restrict__ bb) {
    unsigned* Ws  = (unsigned*)(sm + SM_W);
    unsigned* Wbs = (unsigned*)(sm + SM_WB);
    for (int i = tid; i < 4096; i += 256)
        Ws[(i >> 6) * 72 + (i & 63)] = f2t(Wa[i]);
    for (int i = tid; i < 1024; i += 256)
        Wbs[(i >> 4) * 24 + (i & 15)] = f2t(Wb[i]);
    if (tid < 64) sm[SM_BA + tid] = ba[tid];
    if (tid < 16) sm[SM_BB + tid] = bb[tid];
}

__device__ __forceinline__ void mlp_layer(float* sm, int tid, int e_base,
                                          const int* __restrict__ nidx,
                                          float* __restrict__ lat_out,
                                          float* __restrict__ sum_out) {
    int lane = tid & 31, warp = tid >> 5;
    int g = lane >> 2, t4 = lane & 3;
    int m0 = warp * 16;
    const unsigned* Xs  = (const unsigned*)(sm + SM_X);
    const unsigned* Ws  = (const unsigned*)(sm + SM_W);
    const unsigned* Wbs = (const unsigned*)(sm + SM_WB);
    unsigned* Hs = (unsigned*)(sm + SM_H);

    // ---- phase 1: H[128][64] = relu(X @ Wa + ba) via m16n8k8 tf32 ----
    {
        float dacc[8][4];
#pragma unroll
        for (int n = 0; n < 8; n++) {
            float blo = sm[SM_BA + n * 8 + 2 * t4];
            float bhi = sm[SM_BA + n * 8 + 2 * t4 + 1];
            dacc[n][0] = blo; dacc[n][1] = bhi;
            dacc[n][2] = blo; dacc[n][3] = bhi;
        }
#pragma unroll
        for (int k8 = 0; k8 < 8; k8++) {
            int kb = k8 * 8;
            unsigned a0 = Xs[(m0 + g) * 68 + kb + t4];
            unsigned a1 = Xs[(m0 + g + 8) * 68 + kb + t4];
            unsigned a2 = Xs[(m0 + g) * 68 + kb + t4 + 4];
            unsigned a3 = Xs[(m0 + g + 8) * 68 + kb + t4 + 4];
#pragma unroll
            for (int n = 0; n < 8; n++) {
                unsigned b0 = Ws[(kb + t4) * 72 + n * 8 + g];
                unsigned b1 = Ws[(kb + t4 + 4) * 72 + n * 8 + g];
                mma8(dacc[n], a0, a1, a2, a3, b0, b1);
            }
        }
        // relu + cvt to tf32 + store H
#pragma unroll
        for (int n = 0; n < 8; n++) {
            unsigned lo0 = f2t(fmaxf(dacc[n][0], 0.f));
            unsigned lo1 = f2t(fmaxf(dacc[n][1], 0.f));
            unsigned hi0 = f2t(fmaxf(dacc[n][2], 0.f));
            unsigned hi1 = f2t(fmaxf(dacc[n][3], 0.f));
            ULL p0 = (ULL)lo0 | ((ULL)lo1 << 32);
            ULL p1 = (ULL)hi0 | ((ULL)hi1 << 32);
            *(ULL*)&Hs[(m0 + g) * 68 + n * 8 + 2 * t4] = p0;
            *(ULL*)&Hs[(m0 + g + 8) * 68 + n * 8 + 2 * t4] = p1;
        }
    }
    __syncthreads();

    // ---- phase 2: lat[128][16] = H @ Wb + bb ----
    float facc[2][4];
    {
#pragma unroll
        for (int n = 0; n < 2; n++) {
            float blo = sm[SM_BB + n * 8 + 2 * t4];
            float bhi = sm[SM_BB + n * 8 + 2 * t4 + 1];
            facc[n][0] = blo; facc[n][1] = bhi;
            facc[n][2] = blo; facc[n][3] = bhi;
        }
#pragma unroll
        for (int k8 = 0; k8 < 8; k8++) {
            int kb = k8 * 8;
            unsigned a0 = Hs[(m0 + g) * 68 + kb + t4];
            unsigned a1 = Hs[(m0 + g + 8) * 68 + kb + t4];
            unsigned a2 = Hs[(m0 + g) * 68 + kb + t4 + 4];
            unsigned a3 = Hs[(m0 + g + 8) * 68 + kb + t4 + 4];
#pragma unroll
            for (int n = 0; n < 2; n++) {
                unsigned b0 = Wbs[(kb + t4) * 24 + n * 8 + g];
                unsigned b1 = Wbs[(kb + t4 + 4) * 24 + n * 8 + g];
                mma8(facc[n], a0, a1, a2, a3, b0, b1);
            }
        }
    }
    __syncthreads();   // all H reads done before lat overlays H region
    float* latF = sm + SM_H;
#pragma unroll
    for (int n = 0; n < 2; n++) {
        latF[(m0 + g) * 17 + n * 8 + 2 * t4]         = facc[n][0];
        latF[(m0 + g) * 17 + n * 8 + 2 * t4 + 1]     = facc[n][1];
        latF[(m0 + g + 8) * 17 + n * 8 + 2 * t4]     = facc[n][2];
        latF[(m0 + g + 8) * 17 + n * 8 + 2 * t4 + 1] = facc[n][3];
    }
    __syncthreads();

    // ---- epilogue: softmax, emit latents, segment-sum atomics ----
    float part = 0.f;
    if (tid < 128 && e_base + tid < NTt) {
        int e = e_base + tid;
        float l[16];
        const float* lr = sm + SM_H + tid * 17;
#pragma unroll
        for (int c = 0; c < 16; c++) l[c] = lr[c];
        softmax16(l);
        float4* po = (float4*)(lat_out + (size_t)e * 16);
#pragma unroll
        for (int q = 0; q < 4; q++)
            po[q] = make_float4(l[4 * q], l[4 * q + 1], l[4 * q + 2], l[4 * q + 3]);
        int ix = nidx[e];
#pragma unroll
        for (int k = 1; k < 16; k++)
            red1(&sum_out[ix * k], l[k]);
        part = l[0];
    }
#pragma unroll
    for (int off = 16; off; off >>= 1)
        part += __shfl_down_sync(0xffffffffu, part, off);
    if ((tid & 31) == 0) sm[SM_RED + (tid >> 5)] = part;
    __syncthreads();
    if (tid == 0) {
        float a = 0.f;
#pragma unroll
        for (int i = 0; i < 8; i++) a += sm[SM_RED + i];
        red1(&sum_out[0], a);
    }
    __syncthreads();   // lat region (H) free before next layer writes H
}

__global__ void __launch_bounds__(256)
k_mlp(const int* __restrict__ s_idx, const int* __restrict__ o_idx,
      const float* __restrict__ nhots,
      const float* __restrict__ W1a, const float* __restrict__ b1a,
      const float* __restrict__ W1b, const float* __restrict__ b1b,
      const float* __restrict__ W2a, const float* __restrict__ b2a,
      const float* __restrict__ W2b, const float* __restrict__ b2b,
      float* __restrict__ lat1, float* __restrict__ lat2,
      float* __restrict__ colsum, float* __restrict__ rowsum) {
    extern __shared__ __align__(16) float sm[];
    int tid = threadIdx.x;
    int e_base = blockIdx.x * 128;

    // ---- stage X [128 edges][64] as tf32, row pad 68 (17 uint4) ----
    unsigned* Xs = (unsigned*)(sm + SM_X);
#pragma unroll
    for (int j = 0; j < 8; j++) {
        int idx4 = tid + 256 * j;            // 0..2047 float4 slots
        int e = idx4 >> 4, kq = idx4 & 15;
        float4 v = make_float4(0.f, 0.f, 0.f, 0.f);
        if (e_base + e < NTt)
            v = __ldg((const float4*)(nhots + (size_t)(e_base + e) * 64) + kq);
        uint4 t;
        t.x = f2t(v.x); t.y = f2t(v.y); t.z = f2t(v.z); t.w = f2t(v.w);
        *(uint4*)&Xs[e * 68 + kq * 4] = t;
    }
    stage_w(sm, tid, W1a, b1a, W1b, b1b);
    __syncthreads();

    mlp_layer(sm, tid, e_base, o_idx, lat1, colsum);

    stage_w(sm, tid, W2a, b2a, W2b, b2b);
    __syncthreads();

    mlp_layer(sm, tid, e_base, s_idx, lat2, rowsum);
}

__global__ void k_scatter(const int* __restrict__ s_idx,
                          const int* __restrict__ o_idx) {
    int t = blockIdx.x * blockDim.x + threadIdx.x;
    if (t < NTt) {
        int s = s_idx[t], o = o_idx[t];
        g_perm_s[atomicAdd(&g_cur_s[s], 1)] = t;
        g_perm_o[atomicAdd(&g_cur_o[o], 1)] = t;
    }
}

// ------ layer-1 spmm, warp per o: weights loaded once, red into h[s] ------
__global__ void __launch_bounds__(256)
k_spmm1(const int* __restrict__ s_idx, const float* __restrict__ w1) {
    int w = (blockIdx.x * blockDim.x + threadIdx.x) >> 5;
    int lane = threadIdx.x & 31;
    if (w >= Nn) return;
    int o = w;
    int deg = g_deg_o[o];
    if (deg == 0) return;
    int beg = g_off_o[o], end = beg + deg;

    float wk[16];
#pragma unroll
    for (int k = 0; k < 16; k++) {
        int j = o * k;
        float c = g_colsum[j];
        float inv = (c > 0.f) ? __frcp_rn(c) : 0.f;
        wk[k] = w1[(size_t)j * 32 + lane] * inv;
    }

    int tA = __ldg(&g_perm_o[beg]);
    int tB = (beg + 1 < end) ? __ldg(&g_perm_o[beg + 1]) : tA;
    int s = __ldg(&s_idx[tA]);
    float lv = (lane < 16) ? __ldg(&g_lat1[(size_t)tA * 16 + lane]) : 0.f;
    for (int p = beg; p < end; p++) {
        int tC = (p + 2 < end) ? __ldg(&g_perm_o[p + 2]) : tB;
        int s_n = s; float lv_n = lv;
        if (p + 1 < end) {
            s_n = __ldg(&s_idx[tB]);
            lv_n = (lane < 16) ? __ldg(&g_lat1[(size_t)tB * 16 + lane]) : 0.f;
        }
        float acc = 0.f;
#pragma unroll
        for (int k = 0; k < 16; k++)
            acc += __shfl_sync(0xffffffffu, lv, k) * wk[k];
        red1(&g_h[s * 32 + lane], acc);
        s = s_n; lv = lv_n; tB = tC;
    }
}

// ------------------------- h = relu(h + bias1) -----------------------------
__global__ void k_relu(const float* __restrict__ bias1) {
    int i = blockIdx.x * blockDim.x + threadIdx.x;
    if (i < Nn * Ee)
        g_h[i] = fmaxf(g_h[i] + bias1[i & 31], 0.f);
}

// -------- layer-2 spmm + k=0 reduction, one merged grid -------------------
// blocks [0, NBS): warp per s, k>=1 red4 into h2
// blocks [NBS, NBS+512): grid-stride k=0 reduction into h2 row 0
#define NBS ((Nn + 7) / 8)
__global__ void __launch_bounds__(256)
k_spmm2h(const int* __restrict__ o_idx) {
    __shared__ __align__(16) float stage[8][16 * 32];
    int wid = threadIdx.x >> 5, lane = threadIdx.x & 31;

    if (blockIdx.x >= NBS) {
        // ---- k=0 bin: block-aggregated global reduction ----
        int gw = (blockIdx.x - NBS) * 8 + wid;
        int nw = 512 * 8;
        float acc = 0.f;
        for (int t = gw; t < NTt; t += nw) {
            float l0 = __ldg(&g_lat2[(size_t)t * 16]);
            int o = __ldg(&o_idx[t]);
            acc += l0 * g_h[o * 32 + lane];
        }
        stage[wid][lane] = acc;
        __syncthreads();
        if (wid == 0) {
            float tot = 0.f;
#pragma unroll
            for (int i = 0; i < 8; i++) tot += stage[i][lane];
            red1(&g_h2[lane], tot);
        }
        return;
    }

    int s = blockIdx.x * 8 + wid;
    if (s >= Nn) return;
    int deg = g_deg_s[s];
    if (deg == 0) return;
    int beg = g_off_s[s], end = beg + deg;
    float acc[16];
#pragma unroll
    for (int k = 0; k < 16; k++) acc[k] = 0.f;

    int tA = __ldg(&g_perm_s[beg]);
    int tB = (beg + 1 < end) ? __ldg(&g_perm_s[beg + 1]) : tA;
    int o = __ldg(&o_idx[tA]);
    float lv = (lane < 16) ? __ldg(&g_lat2[(size_t)tA * 16 + lane]) : 0.f;
    for (int p = beg; p < end; p++) {
        int tC = (p + 2 < end) ? __ldg(&g_perm_s[p + 2]) : tB;
        int o_n = o; float lv_n = lv;
        if (p + 1 < end) {
            o_n = __ldg(&o_idx[tB]);
            lv_n = (lane < 16) ? __ldg(&g_lat2[(size_t)tB * 16 + lane]) : 0.f;
        }
        float hv = g_h[o * 32 + lane];
#pragma unroll
        for (int k = 1; k < 16; k++)
            acc[k] += __shfl_sync(0xffffffffu, lv, k) * hv;
        o = o_n; lv = lv_n; tB = tC;
    }
    float* st = stage[wid];
#pragma unroll
    for (int k = 1; k < 16; k++) st[k * 32 + lane] = acc[k];
    __syncwarp();
#pragma unroll
    for (int it = 0; it < 4; it++) {
        int idx = it * 32 + lane;        // 0..127 over 16 rows x 8 float4
        if (idx >= 8) {                  // skip k=0 (handled by k=0 blocks)
            int k = idx >> 3, q = idx & 7;
            float4 v = ((float4*)st)[idx];
            int j = s * k;
            red4(&((float4*)g_h2)[(size_t)j * 8 + q], v);
        }
    }
}

// ------------------- einsum + bias2: out, 2 nodes / thread ----------------
__global__ void __launch_bounds__(256)
k_out(const float* __restrict__ w2, const float* __restrict__ bias2,
      float* __restrict__ out) {
    extern __shared__ __align__(16) float sw2[];   // 16*32*32 floats = 64 KB
    for (int i = threadIdx.x; i < 16 * 32 * 32; i += 256) sw2[i] = w2[i];
    __syncthreads();
    int n0 = blockIdx.x * 256 + threadIdx.x;       // 0..24999
    if (n0 >= Nn / 2) return;
    int n1 = n0 + Nn / 2;
    ULL accA[16], accB[16];
#pragma unroll
    for (int c2 = 0; c2 < 16; c2++) {
        accA[c2] = ((const ULL*)bias2)[c2];
        accB[c2] = accA[c2];
    }
#pragma unroll 1
    for (int r = 0; r < 16; r++) {
        int jA = r * Nn + n0;
        int jB = jA + Nn / 2;
        float ra = g_rowsum[jA], rb = g_rowsum[jB];
        float invA = (ra > 0.f) ? __frcp_rn(ra) : 0.f;
        float invB = (rb > 0.f) ? __frcp_rn(rb) : 0.f;
        const float4* hA = (const float4*)&g_h2[(size_t)jA * 32];
        const float4* hB = (const float4*)&g_h2[(size_t)jB * 32];
#pragma unroll
        for (int e4 = 0; e4 < 8; e4++) {
            float4 va = hA[e4];
            float4 vb = hB[e4];
            float xa[4] = { va.x * invA, va.y * invA, va.z * invA, va.w * invA };
            float xb[4] = { vb.x * invB, vb.y * invB, vb.z * invB, vb.w * invB };
#pragma unroll
            for (int u = 0; u < 4; u++) {
                int e = e4 * 4 + u;
                ULL sa = splat2(xa[u]);
                ULL sb = splat2(xb[u]);
                const float4* wr4 = (const float4*)&sw2[(r * 32 + e) * 32];
#pragma unroll
                for (int c4 = 0; c4 < 8; c4++) {
                    F4U w; w.f = wr4[c4];
                    accA[2 * c4]     = ffma2(sa, w.u[0], accA[2 * c4]);
                    accA[2 * c4 + 1] = ffma2(sa, w.u[1], accA[2 * c4 + 1]);
                    accB[2 * c4]     = ffma2(sb, w.u[0], accB[2 * c4]);
                    accB[2 * c4 + 1] = ffma2(sb, w.u[1], accB[2 * c4 + 1]);
                }
            }
        }
    }
    ULL* opA = (ULL*)(out + (size_t)n0 * 32);
    ULL* opB = (ULL*)(out + (size_t)n1 * 32);
#pragma unroll
    for (int c2 = 0; c2 < 16; c2++) { opA[c2] = accA[c2]; opB[c2] = accB[c2]; }
}

// ------------------------- launch -----------------------------------------
extern "C" void kernel_launch(void* const* d_in, const int* in_sizes, int n_in,
                              void* d_out, int out_size) {
    const int*   s_idx = (const int*)d_in[0];
    const int*   o_idx = (const int*)d_in[1];
    const float* nhots = (const float*)d_in[2];
    const float* W1a   = (const float*)d_in[3];
    const float* b1a   = (const float*)d_in[4];
    const float* W1b   = (const float*)d_in[5];
    const float* b1b   = (const float*)d_in[6];
    const float* W2a   = (const float*)d_in[7];
    const float* b2a   = (const float*)d_in[8];
    const float* W2b   = (const float*)d_in[9];
    const float* b2b   = (const float*)d_in[10];
    const float* w1    = (const float*)d_in[11];
    const float* w2    = (const float*)d_in[12];
    const float* bias1 = (const float*)d_in[13];
    const float* bias2 = (const float*)d_in[14];
    float* out = (float*)d_out;

    static float* lat1p = nullptr;
    static float* lat2p = nullptr;
    static float* colp = nullptr;
    static float* rowp = nullptr;
    static cudaStream_t s1 = nullptr;
    static cudaEvent_t evF = nullptr, evH = nullptr;
    if (!lat1p) {
        cudaGetSymbolAddress((void**)&lat1p, g_lat1);
        cudaGetSymbolAddress((void**)&lat2p, g_lat2);
        cudaGetSymbolAddress((void**)&colp, g_colsum);
        cudaGetSymbolAddress((void**)&rowp, g_rowsum);
        cudaFuncSetAttribute(k_mlp, cudaFuncAttributeMaxDynamicSharedMemorySize,
                             SM_FLOATS * (int)sizeof(float));
        cudaFuncSetAttribute(k_out, cudaFuncAttributeMaxDynamicSharedMemorySize,
                             16 * 32 * 32 * (int)sizeof(float));
        cudaStreamCreateWithFlags(&s1, cudaStreamNonBlocking);
        cudaEventCreateWithFlags(&evF, cudaEventDisableTiming);
        cudaEventCreateWithFlags(&evH, cudaEventDisableTiming);
    }

    int mlp_blocks = (NTt + 127) / 128;
    size_t mlp_smem = SM_FLOATS * sizeof(float);

    k_init_small<<<512, 256>>>();                              // 0
    k_deg<<<(NTt + 255) / 256, 256>>>(s_idx, o_idx);           // 1
    k_alloc<<<(Nn + 255) / 256, 256>>>();                      // 2
    cudaEventRecord(evF, 0);                                   // fork point
    k_mlp<<<mlp_blocks, 256, mlp_smem>>>(s_idx, o_idx, nhots,  // 3 <- ncu slot
                                         W1a, b1a, W1b, b1b,
                                         W2a, b2a, W2b, b2b,
                                         lat1p, lat2p, colp, rowp);
    // side stream: zero h2 concurrently with k_mlp / scatter / spmm1
    cudaStreamWaitEvent(s1, evF, 0);
    k_init_h2<<<2048, 256, 0, s1>>>();                         // 4 (stream s1)
    cudaEventRecord(evH, s1);

    k_scatter<<<(NTt + 255) / 256, 256>>>(s_idx, o_idx);       // 5
    k_spmm1<<<(Nn * 32 + 255) / 256, 256>>>(s_idx, w1);        // 6
    k_relu<<<(Nn * Ee + 255) / 256, 256>>>(bias1);             // 7
    cudaStreamWaitEvent(0, evH, 0);                            // join h2-zero
    k_spmm2h<<<NBS + 512, 256>>>(o_idx);                       // 8
    k_out<<<(Nn / 2 + 255) / 256, 256, 16 * 32 * 32 * (int)sizeof(float)>>>(w2, bias2, out); // 9
}

// round 14
// speedup vs baseline: 1.2403x; 1.0181x over previous
#include <cuda_runtime.h>
#include <cstdint>

#define Nn  50000
#define NTt 300000
#define RPk 16
#define Ee  32
#define Cc  32

// ------------------------- device scratch (static, no allocs) -------------
__device__ float g_lat1[(size_t)NTt * RPk];        // 19.2 MB
__device__ float g_lat2[(size_t)NTt * RPk];        // 19.2 MB
__device__ float g_colsum[Nn * RPk];               // 3.2 MB
__device__ float g_rowsum[Nn * RPk];               // 3.2 MB
__device__ float g_h[Nn * Ee];                     // 6.4 MB
__device__ float g_h2[(size_t)RPk * Nn * Ee];      // 102.4 MB
__device__ int   g_deg_s[Nn];
__device__ int   g_deg_o[Nn];
__device__ int   g_off_s[Nn];
__device__ int   g_off_o[Nn];
__device__ int   g_cur_s[Nn];
__device__ int   g_cur_o[Nn];
__device__ int   g_perm_s[NTt];
__device__ int   g_perm_o[NTt];
__device__ int   g_counter[2];

// ------------------------- small helpers ----------------------------------
typedef unsigned long long ULL;
union F4U { float4 f; ULL u[2]; float s[4]; };

__device__ __forceinline__ ULL splat2(float v) {
    ULL r;
    asm("mov.b64 %0, {%1, %1};" : "=l"(r) : "f"(v));
    return r;
}
__device__ __forceinline__ ULL ffma2(ULL a, ULL b, ULL c) {
    ULL d;
    asm("fma.rn.f32x2 %0, %1, %2, %3;" : "=l"(d) : "l"(a), "l"(b), "l"(c));
    return d;
}
__device__ __forceinline__ void red4(float4* a, float4 v) {
    asm volatile("red.global.add.v4.f32 [%0], {%1, %2, %3, %4};"
                 :: "l"(a), "f"(v.x), "f"(v.y), "f"(v.z), "f"(v.w) : "memory");
}
__device__ __forceinline__ void red1(float* a, float v) {
    asm volatile("red.global.add.f32 [%0], %1;" :: "l"(a), "f"(v) : "memory");
}
// f32 -> tf32 (bits in a b32 reg)
__device__ __forceinline__ unsigned f2t(float f) {
    unsigned r;
    asm("cvt.rna.tf32.f32 %0, %1;" : "=r"(r) : "f"(f));
    return r;
}
// D(16x8,f32) += A(16x8,tf32,row) * B(8x8,tf32,col)
__device__ __forceinline__ void mma8(float* d, unsigned a0, unsigned a1,
                                     unsigned a2, unsigned a3,
                                     unsigned b0, unsigned b1) {
    asm("mma.sync.aligned.m16n8k8.row.col.f32.tf32.tf32.f32 "
        "{%0,%1,%2,%3}, {%4,%5,%6,%7}, {%8,%9}, {%0,%1,%2,%3};"
        : "+f"(d[0]), "+f"(d[1]), "+f"(d[2]), "+f"(d[3])
        : "r"(a0), "r"(a1), "r"(a2), "r"(a3), "r"(b0), "r"(b1));
}

// ------------------- init (small): everything except h2 -------------------
__global__ void k_init_small() {
    size_t i = (size_t)blockIdx.x * blockDim.x + threadIdx.x;
    size_t stride = (size_t)gridDim.x * blockDim.x;
    float4 z = make_float4(0.f, 0.f, 0.f, 0.f);
    for (size_t p = i; p < (size_t)Nn * RPk / 4; p += stride) {
        ((float4*)g_colsum)[p] = z;
        ((float4*)g_rowsum)[p] = z;
    }
    for (size_t p = i; p < (size_t)Nn * Ee / 4; p += stride)
        ((float4*)g_h)[p] = z;
    for (size_t p = i; p < Nn / 4; p += stride) {
        ((int4*)g_deg_s)[p] = make_int4(0, 0, 0, 0);
        ((int4*)g_deg_o)[p] = make_int4(0, 0, 0, 0);
    }
    if (i == 0) { g_counter[0] = 0; g_counter[1] = 0; }
}

// ------------------- init (big): zero h2 (102.4 MB) -----------------------
__global__ void k_init_h2() {
    size_t i = (size_t)blockIdx.x * blockDim.x + threadIdx.x;
    size_t stride = (size_t)gridDim.x * blockDim.x;
    float4 z = make_float4(0.f, 0.f, 0.f, 0.f);
    for (size_t p = i; p < (size_t)RPk * Nn * Ee / 4; p += stride)
        ((float4*)g_h2)[p] = z;
}

// ------------------------- degree count -----------------------------------
__global__ void k_deg(const int* __restrict__ s_idx, const int* __restrict__ o_idx) {
    int t = blockIdx.x * blockDim.x + threadIdx.x;
    if (t < NTt) {
        atomicAdd(&g_deg_s[s_idx[t]], 1);
        atomicAdd(&g_deg_o[o_idx[t]], 1);
    }
}

// ---------------- CSR range allocation (warp-aggregated, unordered) -------
__global__ void k_alloc() {
    int i = blockIdx.x * blockDim.x + threadIdx.x;
    int lane = threadIdx.x & 31;
    int ds = (i < Nn) ? g_deg_s[i] : 0;
    int dq = (i < Nn) ? g_deg_o[i] : 0;
    int ss = ds, so = dq;
#pragma unroll
    for (int off = 1; off < 32; off <<= 1) {
        int a = __shfl_up_sync(0xffffffffu, ss, off);
        int b = __shfl_up_sync(0xffffffffu, so, off);
        if (lane >= off) { ss += a; so += b; }
    }
    int bs = 0, bo = 0;
    if (lane == 31) {
        bs = atomicAdd(&g_counter[0], ss);
        bo = atomicAdd(&g_counter[1], so);
    }
    bs = __shfl_sync(0xffffffffu, bs, 31);
    bo = __shfl_sync(0xffffffffu, bo, 31);
    if (i < Nn) {
        int es = bs + ss - ds;
        int eo = bo + so - dq;
        g_off_s[i] = es; g_cur_s[i] = es;
        g_off_o[i] = eo; g_cur_o[i] = eo;
    }
}

__global__ void k_scatter(const int* __restrict__ s_idx,
                          const int* __restrict__ o_idx) {
    int t = blockIdx.x * blockDim.x + threadIdx.x;
    if (t < NTt) {
        int s = s_idx[t], o = o_idx[t];
        g_perm_s[atomicAdd(&g_cur_s[s], 1)] = t;
        g_perm_o[atomicAdd(&g_cur_o[o], 1)] = t;
    }
}

// --------- fused double-MLP (tf32 tensor cores) + softmax + seg sums ------
// block = 128 edges, 256 threads (8 warps, warp = 16-edge m-stripe).
// smem (32-bit words):
//   X  [128][68] tf32 @ 0      (8704)
//   H  [128][68] tf32 @ 8704   (8704)  -- reused as lat[128][17] f32
//   Wa [64][72]  tf32 @ 17408  (4608)  -- re-staged per layer
//   Wb [64][24]  tf32 @ 22016  (1536)
//   ba [64] f32 @ 23552 ; bb [16] f32 @ 23616 ; red [8] @ 23632
#define SM_X    0
#define SM_H    8704
#define SM_W    17408
#define SM_WB   22016
#define SM_BA   23552
#define SM_BB   23616
#define SM_RED  23632
#define SM_FLOATS 23640

__device__ __forceinline__ void softmax16(float* l) {
    float m = l[0];
#pragma unroll
    for (int k = 1; k < 16; k++) m = fmaxf(m, l[k]);
    float s = 0.f;
#pragma unroll
    for (int k = 0; k < 16; k++) { l[k] = __expf(l[k] - m); s += l[k]; }
    float inv = 1.f / s;
#pragma unroll
    for (int k = 0; k < 16; k++) l[k] *= inv;
}

__device__ __forceinline__ void stage_w(float* sm, int tid,
                                        const float* __restrict__ Wa,
                                        const float* __restrict__ ba,
                                        const float* __restrict__ Wb,
                                        const float* __restrict__ bb) {
    unsigned* Ws  = (unsigned*)(sm + SM_W);
    unsigned* Wbs = (unsigned*)(sm + SM_WB);
    for (int i = tid; i < 4096; i += 256)
        Ws[(i >> 6) * 72 + (i & 63)] = f2t(Wa[i]);
    for (int i = tid; i < 1024; i += 256)
        Wbs[(i >> 4) * 24 + (i & 15)] = f2t(Wb[i]);
    if (tid < 64) sm[SM_BA + tid] = ba[tid];
    if (tid < 16) sm[SM_BB + tid] = bb[tid];
}

__device__ __forceinline__ void mlp_layer(float* sm, int tid, int e_base,
                                          const int* __restrict__ nidx,
                                          float* __restrict__ lat_out,
                                          float* __restrict__ sum_out) {
    int lane = tid & 31, warp = tid >> 5;
    int g = lane >> 2, t4 = lane & 3;
    int m0 = warp * 16;
    const unsigned* Xs  = (const unsigned*)(sm + SM_X);
    const unsigned* Ws  = (const unsigned*)(sm + SM_W);
    const unsigned* Wbs = (const unsigned*)(sm + SM_WB);
    unsigned* Hs = (unsigned*)(sm + SM_H);

    // ---- phase 1: H[128][64] = relu(X @ Wa + ba) via m16n8k8 tf32 ----
    {
        float dacc[8][4];
#pragma unroll
        for (int n = 0; n < 8; n++) {
            float blo = sm[SM_BA + n * 8 + 2 * t4];
            float bhi = sm[SM_BA + n * 8 + 2 * t4 + 1];
            dacc[n][0] = blo; dacc[n][1] = bhi;
            dacc[n][2] = blo; dacc[n][3] = bhi;
        }
#pragma unroll
        for (int k8 = 0; k8 < 8; k8++) {
            int kb = k8 * 8;
            unsigned a0 = Xs[(m0 + g) * 68 + kb + t4];
            unsigned a1 = Xs[(m0 + g + 8) * 68 + kb + t4];
            unsigned a2 = Xs[(m0 + g) * 68 + kb + t4 + 4];
            unsigned a3 = Xs[(m0 + g + 8) * 68 + kb + t4 + 4];
#pragma unroll
            for (int n = 0; n < 8; n++) {
                unsigned b0 = Ws[(kb + t4) * 72 + n * 8 + g];
                unsigned b1 = Ws[(kb + t4 + 4) * 72 + n * 8 + g];
                mma8(dacc[n], a0, a1, a2, a3, b0, b1);
            }
        }
        // relu + cvt to tf32 + store H
#pragma unroll
        for (int n = 0; n < 8; n++) {
            unsigned lo0 = f2t(fmaxf(dacc[n][0], 0.f));
            unsigned lo1 = f2t(fmaxf(dacc[n][1], 0.f));
            unsigned hi0 = f2t(fmaxf(dacc[n][2], 0.f));
            unsigned hi1 = f2t(fmaxf(dacc[n][3], 0.f));
            ULL p0 = (ULL)lo0 | ((ULL)lo1 << 32);
            ULL p1 = (ULL)hi0 | ((ULL)hi1 << 32);
            *(ULL*)&Hs[(m0 + g) * 68 + n * 8 + 2 * t4] = p0;
            *(ULL*)&Hs[(m0 + g + 8) * 68 + n * 8 + 2 * t4] = p1;
        }
    }
    __syncthreads();

    // ---- phase 2: lat[128][16] = H @ Wb + bb ----
    float facc[2][4];
    {
#pragma unroll
        for (int n = 0; n < 2; n++) {
            float blo = sm[SM_BB + n * 8 + 2 * t4];
            float bhi = sm[SM_BB + n * 8 + 2 * t4 + 1];
            facc[n][0] = blo; facc[n][1] = bhi;
            facc[n][2] = blo; facc[n][3] = bhi;
        }
#pragma unroll
        for (int k8 = 0; k8 < 8; k8++) {
            int kb = k8 * 8;
            unsigned a0 = Hs[(m0 + g) * 68 + kb + t4];
            unsigned a1 = Hs[(m0 + g + 8) * 68 + kb + t4];
            unsigned a2 = Hs[(m0 + g) * 68 + kb + t4 + 4];
            unsigned a3 = Hs[(m0 + g + 8) * 68 + kb + t4 + 4];
#pragma unroll
            for (int n = 0; n < 2; n++) {
                unsigned b0 = Wbs[(kb + t4) * 24 + n * 8 + g];
                unsigned b1 = Wbs[(kb + t4 + 4) * 24 + n * 8 + g];
                mma8(facc[n], a0, a1, a2, a3, b0, b1);
            }
        }
    }
    __syncthreads();   // all H reads done before lat overlays H region
    float* latF = sm + SM_H;
#pragma unroll
    for (int n = 0; n < 2; n++) {
        latF[(m0 + g) * 17 + n * 8 + 2 * t4]         = facc[n][0];
        latF[(m0 + g) * 17 + n * 8 + 2 * t4 + 1]     = facc[n][1];
        latF[(m0 + g + 8) * 17 + n * 8 + 2 * t4]     = facc[n][2];
        latF[(m0 + g + 8) * 17 + n * 8 + 2 * t4 + 1] = facc[n][3];
    }
    __syncthreads();

    // ---- epilogue: softmax, emit latents, segment-sum atomics ----
    float part = 0.f;
    if (tid < 128 && e_base + tid < NTt) {
        int e = e_base + tid;
        float l[16];
        const float* lr = sm + SM_H + tid * 17;
#pragma unroll
        for (int c = 0; c < 16; c++) l[c] = lr[c];
        softmax16(l);
        float4* po = (float4*)(lat_out + (size_t)e * 16);
#pragma unroll
        for (int q = 0; q < 4; q++)
            po[q] = make_float4(l[4 * q], l[4 * q + 1], l[4 * q + 2], l[4 * q + 3]);
        int ix = nidx[e];
#pragma unroll
        for (int k = 1; k < 16; k++)
            red1(&sum_out[ix * k], l[k]);
        part = l[0];
    }
#pragma unroll
    for (int off = 16; off; off >>= 1)
        part += __shfl_down_sync(0xffffffffu, part, off);
    if ((tid & 31) == 0) sm[SM_RED + (tid >> 5)] = part;
    __syncthreads();
    if (tid == 0) {
        float a = 0.f;
#pragma unroll
        for (int i = 0; i < 8; i++) a += sm[SM_RED + i];
        red1(&sum_out[0], a);
    }
    __syncthreads();   // lat region (H) free before next layer writes H
}

__global__ void __launch_bounds__(256)
k_mlp(const int* __restrict__ s_idx, const int* __restrict__ o_idx,
      const float* __restrict__ nhots,
      const float* __restrict__ W1a, const float* __restrict__ b1a,
      const float* __restrict__ W1b, const float* __restrict__ b1b,
      const float* __restrict__ W2a, const float* __restrict__ b2a,
      const float* __restrict__ W2b, const float* __restrict__ b2b,
      float* __restrict__ lat1, float* __restrict__ lat2,
      float* __restrict__ colsum, float* __restrict__ rowsum) {
    extern __shared__ __align__(16) float sm[];
    int tid = threadIdx.x;
    int e_base = blockIdx.x * 128;

    // ---- stage X [128 edges][64] as tf32, row pad 68 (17 uint4) ----
    unsigned* Xs = (unsigned*)(sm + SM_X);
#pragma unroll
    for (int j = 0; j < 8; j++) {
        int idx4 = tid + 256 * j;            // 0..2047 float4 slots
        int e = idx4 >> 4, kq = idx4 & 15;
        float4 v = make_float4(0.f, 0.f, 0.f, 0.f);
        if (e_base + e < NTt)
            v = __ldg((const float4*)(nhots + (size_t)(e_base + e) * 64) + kq);
        uint4 t;
        t.x = f2t(v.x); t.y = f2t(v.y); t.z = f2t(v.z); t.w = f2t(v.w);
        *(uint4*)&Xs[e * 68 + kq * 4] = t;
    }
    stage_w(sm, tid, W1a, b1a, W1b, b1b);
    __syncthreads();

    mlp_layer(sm, tid, e_base, o_idx, lat1, colsum);

    stage_w(sm, tid, W2a, b2a, W2b, b2b);
    __syncthreads();

    mlp_layer(sm, tid, e_base, s_idx, lat2, rowsum);
}

// ------ layer-1 spmm, warp per o: weights loaded once, red into h[s] ------
__global__ void __launch_bounds__(256)
k_spmm1(const int* __restrict__ s_idx, const float* __restrict__ w1) {
    int w = (blockIdx.x * blockDim.x + threadIdx.x) >> 5;
    int lane = threadIdx.x & 31;
    if (w >= Nn) return;
    int o = w;
    int deg = g_deg_o[o];
    if (deg == 0) return;
    int beg = g_off_o[o], end = beg + deg;

    float wk[16];
#pragma unroll
    for (int k = 0; k < 16; k++) {
        int j = o * k;
        float c = g_colsum[j];
        float inv = (c > 0.f) ? __frcp_rn(c) : 0.f;
        wk[k] = w1[(size_t)j * 32 + lane] * inv;
    }

    int tA = __ldg(&g_perm_o[beg]);
    int tB = (beg + 1 < end) ? __ldg(&g_perm_o[beg + 1]) : tA;
    int s = __ldg(&s_idx[tA]);
    float lv = (lane < 16) ? __ldg(&g_lat1[(size_t)tA * 16 + lane]) : 0.f;
    for (int p = beg; p < end; p++) {
        int tC = (p + 2 < end) ? __ldg(&g_perm_o[p + 2]) : tB;
        int s_n = s; float lv_n = lv;
        if (p + 1 < end) {
            s_n = __ldg(&s_idx[tB]);
            lv_n = (lane < 16) ? __ldg(&g_lat1[(size_t)tB * 16 + lane]) : 0.f;
        }
        float acc = 0.f;
#pragma unroll
        for (int k = 0; k < 16; k++)
            acc += __shfl_sync(0xffffffffu, lv, k) * wk[k];
        red1(&g_h[s * 32 + lane], acc);
        s = s_n; lv = lv_n; tB = tC;
    }
}

// ------------------------- h = relu(h + bias1) -----------------------------
__global__ void k_relu(const float* __restrict__ bias1) {
    int i = blockIdx.x * blockDim.x + threadIdx.x;
    if (i < Nn * Ee)
        g_h[i] = fmaxf(g_h[i] + bias1[i & 31], 0.f);
}

// -------- layer-2 spmm + k=0 reduction, one merged grid -------------------
// blocks [0, NBS): warp per s, k>=1 red4 into h2
// blocks [NBS, NBS+512): grid-stride k=0 reduction into h2 row 0
#define NBS ((Nn + 7) / 8)
__global__ void __launch_bounds__(256)
k_spmm2h(const int* __restrict__ o_idx) {
    __shared__ __align__(16) float stage[8][16 * 32];
    int wid = threadIdx.x >> 5, lane = threadIdx.x & 31;

    if (blockIdx.x >= NBS) {
        // ---- k=0 bin: block-aggregated global reduction ----
        int gw = (blockIdx.x - NBS) * 8 + wid;
        int nw = 512 * 8;
        float acc = 0.f;
        for (int t = gw; t < NTt; t += nw) {
            float l0 = __ldg(&g_lat2[(size_t)t * 16]);
            int o = __ldg(&o_idx[t]);
            acc += l0 * g_h[o * 32 + lane];
        }
        stage[wid][lane] = acc;
        __syncthreads();
        if (wid == 0) {
            float tot = 0.f;
#pragma unroll
            for (int i = 0; i < 8; i++) tot += stage[i][lane];
            red1(&g_h2[lane], tot);
        }
        return;
    }

    int s = blockIdx.x * 8 + wid;
    if (s >= Nn) return;
    int deg = g_deg_s[s];
    if (deg == 0) return;
    int beg = g_off_s[s], end = beg + deg;
    float acc[16];
#pragma unroll
    for (int k = 0; k < 16; k++) acc[k] = 0.f;

    int tA = __ldg(&g_perm_s[beg]);
    int tB = (beg + 1 < end) ? __ldg(&g_perm_s[beg + 1]) : tA;
    int o = __ldg(&o_idx[tA]);
    float lv = (lane < 16) ? __ldg(&g_lat2[(size_t)tA * 16 + lane]) : 0.f;
    for (int p = beg; p < end; p++) {
        int tC = (p + 2 < end) ? __ldg(&g_perm_s[p + 2]) : tB;
        int o_n = o; float lv_n = lv;
        if (p + 1 < end) {
            o_n = __ldg(&o_idx[tB]);
            lv_n = (lane < 16) ? __ldg(&g_lat2[(size_t)tB * 16 + lane]) : 0.f;
        }
        float hv = g_h[o * 32 + lane];
#pragma unroll
        for (int k = 1; k < 16; k++)
            acc[k] += __shfl_sync(0xffffffffu, lv, k) * hv;
        o = o_n; lv = lv_n; tB = tC;
    }
    float* st = stage[wid];
#pragma unroll
    for (int k = 1; k < 16; k++) st[k * 32 + lane] = acc[k];
    __syncwarp();
#pragma unroll
    for (int it = 0; it < 4; it++) {
        int idx = it * 32 + lane;        // 0..127 over 16 rows x 8 float4
        if (idx >= 8) {                  // skip k=0 (handled by k=0 blocks)
            int k = idx >> 3, q = idx & 7;
            float4 v = ((float4*)st)[idx];
            int j = s * k;
            red4(&((float4*)g_h2)[(size_t)j * 8 + q], v);
        }
    }
}

// ------------------- einsum + bias2: out, 2 nodes / thread ----------------
__global__ void __launch_bounds__(256)
k_out(const float* __restrict__ w2, const float* __restrict__ bias2,
      float* __restrict__ out) {
    extern __shared__ __align__(16) float sw2[];   // 16*32*32 floats = 64 KB
    for (int i = threadIdx.x; i < 16 * 32 * 32; i += 256) sw2[i] = w2[i];
    __syncthreads();
    int n0 = blockIdx.x * 256 + threadIdx.x;       // 0..24999
    if (n0 >= Nn / 2) return;
    int n1 = n0 + Nn / 2;
    ULL accA[16], accB[16];
#pragma unroll
    for (int c2 = 0; c2 < 16; c2++) {
        accA[c2] = ((const ULL*)bias2)[c2];
        accB[c2] = accA[c2];
    }
#pragma unroll 1
    for (int r = 0; r < 16; r++) {
        int jA = r * Nn + n0;
        int jB = jA + Nn / 2;
        float ra = g_rowsum[jA], rb = g_rowsum[jB];
        float invA = (ra > 0.f) ? __frcp_rn(ra) : 0.f;
        float invB = (rb > 0.f) ? __frcp_rn(rb) : 0.f;
        const float4* hA = (const float4*)&g_h2[(size_t)jA * 32];
        const float4* hB = (const float4*)&g_h2[(size_t)jB * 32];
#pragma unroll
        for (int e4 = 0; e4 < 8; e4++) {
            float4 va = hA[e4];
            float4 vb = hB[e4];
            float xa[4] = { va.x * invA, va.y * invA, va.z * invA, va.w * invA };
            float xb[4] = { vb.x * invB, vb.y * invB, vb.z * invB, vb.w * invB };
#pragma unroll
            for (int u = 0; u < 4; u++) {
                int e = e4 * 4 + u;
                ULL sa = splat2(xa[u]);
                ULL sb = splat2(xb[u]);
                const float4* wr4 = (const float4*)&sw2[(r * 32 + e) * 32];
#pragma unroll
                for (int c4 = 0; c4 < 8; c4++) {
                    F4U w; w.f = wr4[c4];
                    accA[2 * c4]     = ffma2(sa, w.u[0], accA[2 * c4]);
                    accA[2 * c4 + 1] = ffma2(sa, w.u[1], accA[2 * c4 + 1]);
                    accB[2 * c4]     = ffma2(sb, w.u[0], accB[2 * c4]);
                    accB[2 * c4 + 1] = ffma2(sb, w.u[1], accB[2 * c4 + 1]);
                }
            }
        }
    }
    ULL* opA = (ULL*)(out + (size_t)n0 * 32);
    ULL* opB = (ULL*)(out + (size_t)n1 * 32);
#pragma unroll
    for (int c2 = 0; c2 < 16; c2++) { opA[c2] = accA[c2]; opB[c2] = accB[c2]; }
}

// ------------------------- launch -----------------------------------------
extern "C" void kernel_launch(void* const* d_in, const int* in_sizes, int n_in,
                              void* d_out, int out_size) {
    const int*   s_idx = (const int*)d_in[0];
    const int*   o_idx = (const int*)d_in[1];
    const float* nhots = (const float*)d_in[2];
    const float* W1a   = (const float*)d_in[3];
    const float* b1a   = (const float*)d_in[4];
    const float* W1b   = (const float*)d_in[5];
    const float* b1b   = (const float*)d_in[6];
    const float* W2a   = (const float*)d_in[7];
    const float* b2a   = (const float*)d_in[8];
    const float* W2b   = (const float*)d_in[9];
    const float* b2b   = (const float*)d_in[10];
    const float* w1    = (const float*)d_in[11];
    const float* w2    = (const float*)d_in[12];
    const float* bias1 = (const float*)d_in[13];
    const float* bias2 = (const float*)d_in[14];
    float* out = (float*)d_out;

    static float* lat1p = nullptr;
    static float* lat2p = nullptr;
    static float* colp = nullptr;
    static float* rowp = nullptr;
    static cudaStream_t s1 = nullptr;
    static cudaEvent_t evF = nullptr, evS = nullptr, evH = nullptr;
    if (!lat1p) {
        cudaGetSymbolAddress((void**)&lat1p, g_lat1);
        cudaGetSymbolAddress((void**)&lat2p, g_lat2);
        cudaGetSymbolAddress((void**)&colp, g_colsum);
        cudaGetSymbolAddress((void**)&rowp, g_rowsum);
        cudaFuncSetAttribute(k_mlp, cudaFuncAttributeMaxDynamicSharedMemorySize,
                             SM_FLOATS * (int)sizeof(float));
        cudaFuncSetAttribute(k_out, cudaFuncAttributeMaxDynamicSharedMemorySize,
                             16 * 32 * 32 * (int)sizeof(float));
        cudaStreamCreateWithFlags(&s1, cudaStreamNonBlocking);
        cudaEventCreateWithFlags(&evF, cudaEventDisableTiming);
        cudaEventCreateWithFlags(&evS, cudaEventDisableTiming);
        cudaEventCreateWithFlags(&evH, cudaEventDisableTiming);
    }

    int mlp_blocks = (NTt + 127) / 128;
    size_t mlp_smem = SM_FLOATS * sizeof(float);

    k_init_small<<<512, 256>>>();                              // 0
    cudaEventRecord(evF, 0);                                   // fork point

    // side stream: CSR build + h2 zero, concurrent with k_mlp
    cudaStreamWaitEvent(s1, evF, 0);
    k_deg<<<(NTt + 255) / 256, 256, 0, s1>>>(s_idx, o_idx);
    k_alloc<<<(Nn + 255) / 256, 256, 0, s1>>>();
    k_scatter<<<(NTt + 255) / 256, 256, 0, s1>>>(s_idx, o_idx);
    cudaEventRecord(evS, s1);
    k_init_h2<<<2048, 256, 0, s1>>>();
    cudaEventRecord(evH, s1);

    // main stream: MLP -> spmm1 -> relu -> spmm2 -> out
    k_mlp<<<mlp_blocks, 256, mlp_smem>>>(s_idx, o_idx, nhots,
                                         W1a, b1a, W1b, b1b,
                                         W2a, b2a, W2b, b2b,
                                         lat1p, lat2p, colp, rowp);
    cudaStreamWaitEvent(0, evS, 0);                            // join CSR build
    k_spmm1<<<(Nn * 32 + 255) / 256, 256>>>(s_idx, w1);
    k_relu<<<(Nn * Ee + 255) / 256, 256>>>(bias1);
    cudaStreamWaitEvent(0, evH, 0);                            // join h2-zero
    k_spmm2h<<<NBS + 512, 256>>>(o_idx);
    k_out<<<(Nn / 2 + 255) / 256, 256, 16 * 32 * 32 * (int)sizeof(float)>>>(w2, bias2, out);
}

// round 15
// speedup vs baseline: 1.2883x; 1.0387x over previous
#include <cuda_runtime.h>
#include <cstdint>

#define Nn  50000
#define NTt 300000
#define RPk 16
#define Ee  32
#define Cc  32

// ------------------------- device scratch (static, no allocs) -------------
__device__ float g_lat1[(size_t)NTt * RPk];        // 19.2 MB
__device__ float g_lat2[(size_t)NTt * RPk];        // 19.2 MB
__device__ float g_colsum[Nn * RPk];               // 3.2 MB
__device__ float g_rowsum[Nn * RPk];               // 3.2 MB
__device__ float g_h[Nn * Ee];                     // 6.4 MB (pre-activation)
__device__ float g_h2[(size_t)RPk * Nn * Ee];      // 102.4 MB
__device__ int   g_deg_s[Nn];
__device__ int   g_deg_o[Nn];
__device__ int   g_off_s[Nn];
__device__ int   g_off_o[Nn];
__device__ int   g_cur_s[Nn];
__device__ int   g_cur_o[Nn];
__device__ int   g_perm_s[NTt];
__device__ int   g_perm_o[NTt];
__device__ int   g_counter[2];

// ------------------------- small helpers ----------------------------------
typedef unsigned long long ULL;
union F4U { float4 f; ULL u[2]; float s[4]; };

__device__ __forceinline__ ULL splat2(float v) {
    ULL r;
    asm("mov.b64 %0, {%1, %1};" : "=l"(r) : "f"(v));
    return r;
}
__device__ __forceinline__ ULL ffma2(ULL a, ULL b, ULL c) {
    ULL d;
    asm("fma.rn.f32x2 %0, %1, %2, %3;" : "=l"(d) : "l"(a), "l"(b), "l"(c));
    return d;
}
__device__ __forceinline__ void red4(float4* a, float4 v) {
    asm volatile("red.global.add.v4.f32 [%0], {%1, %2, %3, %4};"
                 :: "l"(a), "f"(v.x), "f"(v.y), "f"(v.z), "f"(v.w) : "memory");
}
__device__ __forceinline__ void red1(float* a, float v) {
    asm volatile("red.global.add.f32 [%0], %1;" :: "l"(a), "f"(v) : "memory");
}
// f32 -> tf32 (bits in a b32 reg)
__device__ __forceinline__ unsigned f2t(float f) {
    unsigned r;
    asm("cvt.rna.tf32.f32 %0, %1;" : "=r"(r) : "f"(f));
    return r;
}
// D(16x8,f32) += A(16x8,tf32,row) * B(8x8,tf32,col)
__device__ __forceinline__ void mma8(float* d, unsigned a0, unsigned a1,
                                     unsigned a2, unsigned a3,
                                     unsigned b0, unsigned b1) {
    asm("mma.sync.aligned.m16n8k8.row.col.f32.tf32.tf32.f32 "
        "{%0,%1,%2,%3}, {%4,%5,%6,%7}, {%8,%9}, {%0,%1,%2,%3};"
        : "+f"(d[0]), "+f"(d[1]), "+f"(d[2]), "+f"(d[3])
        : "r"(a0), "r"(a1), "r"(a2), "r"(a3), "r"(b0), "r"(b1));
}

// ------------------- init (small): everything except h2 -------------------
__global__ void k_init_small() {
    size_t i = (size_t)blockIdx.x * blockDim.x + threadIdx.x;
    size_t stride = (size_t)gridDim.x * blockDim.x;
    float4 z = make_float4(0.f, 0.f, 0.f, 0.f);
    for (size_t p = i; p < (size_t)Nn * RPk / 4; p += stride) {
        ((float4*)g_colsum)[p] = z;
        ((float4*)g_rowsum)[p] = z;
    }
    for (size_t p = i; p < (size_t)Nn * Ee / 4; p += stride)
        ((float4*)g_h)[p] = z;
    for (size_t p = i; p < Nn / 4; p += stride) {
        ((int4*)g_deg_s)[p] = make_int4(0, 0, 0, 0);
        ((int4*)g_deg_o)[p] = make_int4(0, 0, 0, 0);
    }
    if (i == 0) { g_counter[0] = 0; g_counter[1] = 0; }
}

// ------------------- init (big): zero h2 (102.4 MB) -----------------------
__global__ void k_init_h2() {
    size_t i = (size_t)blockIdx.x * blockDim.x + threadIdx.x;
    size_t stride = (size_t)gridDim.x * blockDim.x;
    float4 z = make_float4(0.f, 0.f, 0.f, 0.f);
    for (size_t p = i; p < (size_t)RPk * Nn * Ee / 4; p += stride)
        ((float4*)g_h2)[p] = z;
}

// ------------------------- degree count -----------------------------------
__global__ void k_deg(const int* __restrict__ s_idx, const int* __restrict__ o_idx) {
    int t = blockIdx.x * blockDim.x + threadIdx.x;
    if (t < NTt) {
        atomicAdd(&g_deg_s[s_idx[t]], 1);
        atomicAdd(&g_deg_o[o_idx[t]], 1);
    }
}

// ---------------- CSR range allocation (warp-aggregated, unordered) -------
__global__ void k_alloc() {
    int i = blockIdx.x * blockDim.x + threadIdx.x;
    int lane = threadIdx.x & 31;
    int ds = (i < Nn) ? g_deg_s[i] : 0;
    int dq = (i < Nn) ? g_deg_o[i] : 0;
    int ss = ds, so = dq;
#pragma unroll
    for (int off = 1; off < 32; off <<= 1) {
        int a = __shfl_up_sync(0xffffffffu, ss, off);
        int b = __shfl_up_sync(0xffffffffu, so, off);
        if (lane >= off) { ss += a; so += b; }
    }
    int bs = 0, bo = 0;
    if (lane == 31) {
        bs = atomicAdd(&g_counter[0], ss);
        bo = atomicAdd(&g_counter[1], so);
    }
    bs = __shfl_sync(0xffffffffu, bs, 31);
    bo = __shfl_sync(0xffffffffu, bo, 31);
    if (i < Nn) {
        int es = bs + ss - ds;
        int eo = bo + so - dq;
        g_off_s[i] = es; g_cur_s[i] = es;
        g_off_o[i] = eo; g_cur_o[i] = eo;
    }
}

__global__ void k_scatter(const int* __restrict__ s_idx,
                          const int* __restrict__ o_idx) {
    int t = blockIdx.x * blockDim.x + threadIdx.x;
    if (t < NTt) {
        int s = s_idx[t], o = o_idx[t];
        g_perm_s[atomicAdd(&g_cur_s[s], 1)] = t;
        g_perm_o[atomicAdd(&g_cur_o[o], 1)] = t;
    }
}

// --------- fused double-MLP (tf32 tensor cores) + softmax + seg sums ------
// block = 128 edges, 256 threads (8 warps, warp = 16-edge m-stripe).
// A-fragments preloaded into registers once (X identical for both layers);
// the X buffer is then reused for H.
// smem (32-bit words), 14936 = 59.7 KB -> 3 blocks/SM:
//   H  [128][68] @ 0     (8704)  -- X during staging; reused as lat[128][17]
//   Wa [64][72]  tf32 @ 8704  (4608)  -- re-staged per layer
//   Wb [64][24]  tf32 @ 13312 (1536)
//   ba [64] @ 14848 ; bb [16] @ 14912 ; red [8] @ 14928
#define SM_H    0
#define SM_W    8704
#define SM_WB   13312
#define SM_BA   14848
#define SM_BB   14912
#define SM_RED  14928
#define SM_FLOATS 14936

__device__ __forceinline__ void softmax16(float* l) {
    float m = l[0];
#pragma unroll
    for (int k = 1; k < 16; k++) m = fmaxf(m, l[k]);
    float s = 0.f;
#pragma unroll
    for (int k = 0; k < 16; k++) { l[k] = __expf(l[k] - m); s += l[k]; }
    float inv = 1.f / s;
#pragma unroll
    for (int k = 0; k < 16; k++) l[k] *= inv;
}

__device__ __forceinline__ void stage_w(float* sm, int tid,
                                        const float* __restrict__ Wa,
                                        const float* __restrict__ ba,
                                        const float* __restrict__ Wb,
                                        const float* __restrict__ bb) {
    unsigned* Ws  = (unsigned*)(sm + SM_W);
    unsigned* Wbs = (unsigned*)(sm + SM_WB);
    for (int i = tid; i < 4096; i += 256)
        Ws[(i >> 6) * 72 + (i & 63)] = f2t(Wa[i]);
    for (int i = tid; i < 1024; i += 256)
        Wbs[(i >> 4) * 24 + (i & 15)] = f2t(Wb[i]);
    if (tid < 64) sm[SM_BA + tid] = ba[tid];
    if (tid < 16) sm[SM_BB + tid] = bb[tid];
}

__device__ __forceinline__ void mlp_layer(float* sm, int tid, int e_base,
                                          const unsigned aR[8][4],
                                          const int* __restrict__ nidx,
                                          float* __restrict__ lat_out,
                                          float* __restrict__ sum_out) {
    int lane = tid & 31, warp = tid >> 5;
    int g = lane >> 2, t4 = lane & 3;
    int m0 = warp * 16;
    const unsigned* Ws  = (const unsigned*)(sm + SM_W);
    const unsigned* Wbs = (const unsigned*)(sm + SM_WB);
    unsigned* Hs = (unsigned*)(sm + SM_H);

    // ---- phase 1: H[128][64] = relu(X @ Wa + ba); A from registers ----
    {
        float dacc[8][4];
#pragma unroll
        for (int n = 0; n < 8; n++) {
            float blo = sm[SM_BA + n * 8 + 2 * t4];
            float bhi = sm[SM_BA + n * 8 + 2 * t4 + 1];
            dacc[n][0] = blo; dacc[n][1] = bhi;
            dacc[n][2] = blo; dacc[n][3] = bhi;
        }
#pragma unroll
        for (int k8 = 0; k8 < 8; k8++) {
            int kb = k8 * 8;
#pragma unroll
            for (int n = 0; n < 8; n++) {
                unsigned b0 = Ws[(kb + t4) * 72 + n * 8 + g];
                unsigned b1 = Ws[(kb + t4 + 4) * 72 + n * 8 + g];
                mma8(dacc[n], aR[k8][0], aR[k8][1], aR[k8][2], aR[k8][3], b0, b1);
            }
        }
        // relu + cvt to tf32 + store H (overwrites X region; A is in regs)
#pragma unroll
        for (int n = 0; n < 8; n++) {
            unsigned lo0 = f2t(fmaxf(dacc[n][0], 0.f));
            unsigned lo1 = f2t(fmaxf(dacc[n][1], 0.f));
            unsigned hi0 = f2t(fmaxf(dacc[n][2], 0.f));
            unsigned hi1 = f2t(fmaxf(dacc[n][3], 0.f));
            ULL p0 = (ULL)lo0 | ((ULL)lo1 << 32);
            ULL p1 = (ULL)hi0 | ((ULL)hi1 << 32);
            *(ULL*)&Hs[(m0 + g) * 68 + n * 8 + 2 * t4] = p0;
            *(ULL*)&Hs[(m0 + g + 8) * 68 + n * 8 + 2 * t4] = p1;
        }
    }
    __syncthreads();

    // ---- phase 2: lat[128][16] = H @ Wb + bb ----
    float facc[2][4];
    {
#pragma unroll
        for (int n = 0; n < 2; n++) {
            float blo = sm[SM_BB + n * 8 + 2 * t4];
            float bhi = sm[SM_BB + n * 8 + 2 * t4 + 1];
            facc[n][0] = blo; facc[n][1] = bhi;
            facc[n][2] = blo; facc[n][3] = bhi;
        }
#pragma unroll
        for (int k8 = 0; k8 < 8; k8++) {
            int kb = k8 * 8;
            unsigned a0 = Hs[(m0 + g) * 68 + kb + t4];
            unsigned a1 = Hs[(m0 + g + 8) * 68 + kb + t4];
            unsigned a2 = Hs[(m0 + g) * 68 + kb + t4 + 4];
            unsigned a3 = Hs[(m0 + g + 8) * 68 + kb + t4 + 4];
#pragma unroll
            for (int n = 0; n < 2; n++) {
                unsigned b0 = Wbs[(kb + t4) * 24 + n * 8 + g];
                unsigned b1 = Wbs[(kb + t4 + 4) * 24 + n * 8 + g];
                mma8(facc[n], a0, a1, a2, a3, b0, b1);
            }
        }
    }
    __syncthreads();   // all H reads done before lat overlays H region
    float* latF = sm + SM_H;
#pragma unroll
    for (int n = 0; n < 2; n++) {
        latF[(m0 + g) * 17 + n * 8 + 2 * t4]         = facc[n][0];
        latF[(m0 + g) * 17 + n * 8 + 2 * t4 + 1]     = facc[n][1];
        latF[(m0 + g + 8) * 17 + n * 8 + 2 * t4]     = facc[n][2];
        latF[(m0 + g + 8) * 17 + n * 8 + 2 * t4 + 1] = facc[n][3];
    }
    __syncthreads();

    // ---- epilogue: softmax, emit latents, segment-sum atomics ----
    float part = 0.f;
    if (tid < 128 && e_base + tid < NTt) {
        int e = e_base + tid;
        float l[16];
        const float* lr = sm + SM_H + tid * 17;
#pragma unroll
        for (int c = 0; c < 16; c++) l[c] = lr[c];
        softmax16(l);
        float4* po = (float4*)(lat_out + (size_t)e * 16);
#pragma unroll
        for (int q = 0; q < 4; q++)
            po[q] = make_float4(l[4 * q], l[4 * q + 1], l[4 * q + 2], l[4 * q + 3]);
        int ix = nidx[e];
#pragma unroll
        for (int k = 1; k < 16; k++)
            red1(&sum_out[ix * k], l[k]);
        part = l[0];
    }
#pragma unroll
    for (int off = 16; off; off >>= 1)
        part += __shfl_down_sync(0xffffffffu, part, off);
    if ((tid & 31) == 0) sm[SM_RED + (tid >> 5)] = part;
    __syncthreads();
    if (tid == 0) {
        float a = 0.f;
#pragma unroll
        for (int i = 0; i < 8; i++) a += sm[SM_RED + i];
        red1(&sum_out[0], a);
    }
    __syncthreads();   // lat region (H) free before next layer writes H
}

__global__ void __launch_bounds__(256, 3)
k_mlp(const int* __restrict__ s_idx, const int* __restrict__ o_idx,
      const float* __restrict__ nhots,
      const float* __restrict__ W1a, const float* __restrict__ b1a,
      const float* __restrict__ W1b, const float* __restrict__ b1b,
      const float* __restrict__ W2a, const float* __restrict__ b2a,
      const float* __restrict__ W2b, const float* __restrict__ b2b,
      float* __restrict__ lat1, float* __restrict__ lat2,
      float* __restrict__ colsum, float* __restrict__ rowsum) {
    extern __shared__ __align__(16) float sm[];
    int tid = threadIdx.x;
    int e_base = blockIdx.x * 128;

    // ---- stage X [128 edges][64] as tf32 into the H region, pad 68 ----
    unsigned* Xs = (unsigned*)(sm + SM_H);
#pragma unroll
    for (int j = 0; j < 8; j++) {
        int idx4 = tid + 256 * j;            // 0..2047 float4 slots
        int e = idx4 >> 4, kq = idx4 & 15;
        float4 v = make_float4(0.f, 0.f, 0.f, 0.f);
        if (e_base + e < NTt)
            v = __ldg((const float4*)(nhots + (size_t)(e_base + e) * 64) + kq);
        uint4 t;
        t.x = f2t(v.x); t.y = f2t(v.y); t.z = f2t(v.z); t.w = f2t(v.w);
        *(uint4*)&Xs[e * 68 + kq * 4] = t;
    }
    stage_w(sm, tid, W1a, b1a, W1b, b1b);
    __syncthreads();

    // ---- preload A-fragments to registers (used by both layers) ----
    unsigned aR[8][4];
    {
        int lane = tid & 31, warp = tid >> 5;
        int g = lane >> 2, t4 = lane & 3;
        int m0 = warp * 16;
#pragma unroll
        for (int k8 = 0; k8 < 8; k8++) {
            int kb = k8 * 8;
            aR[k8][0] = Xs[(m0 + g) * 68 + kb + t4];
            aR[k8][1] = Xs[(m0 + g + 8) * 68 + kb + t4];
            aR[k8][2] = Xs[(m0 + g) * 68 + kb + t4 + 4];
            aR[k8][3] = Xs[(m0 + g + 8) * 68 + kb + t4 + 4];
        }
    }
    __syncthreads();   // all X reads done before phase 1 overwrites with H

    mlp_layer(sm, tid, e_base, aR, o_idx, lat1, colsum);

    stage_w(sm, tid, W2a, b2a, W2b, b2b);
    __syncthreads();

    mlp_layer(sm, tid, e_base, aR, s_idx, lat2, rowsum);
}

// ------ layer-1 spmm, warp per o: weights loaded once, red into h[s] ------
__global__ void __launch_bounds__(256)
k_spmm1(const int* __restrict__ s_idx, const float* __restrict__ w1) {
    int w = (blockIdx.x * blockDim.x + threadIdx.x) >> 5;
    int lane = threadIdx.x & 31;
    if (w >= Nn) return;
    int o = w;
    int deg = g_deg_o[o];
    if (deg == 0) return;
    int beg = g_off_o[o], end = beg + deg;

    float wk[16];
#pragma unroll
    for (int k = 0; k < 16; k++) {
        int j = o * k;
        float c = g_colsum[j];
        float inv = (c > 0.f) ? __frcp_rn(c) : 0.f;
        wk[k] = w1[(size_t)j * 32 + lane] * inv;
    }

    int tA = __ldg(&g_perm_o[beg]);
    int tB = (beg + 1 < end) ? __ldg(&g_perm_o[beg + 1]) : tA;
    int s = __ldg(&s_idx[tA]);
    float lv = (lane < 16) ? __ldg(&g_lat1[(size_t)tA * 16 + lane]) : 0.f;
    for (int p = beg; p < end; p++) {
        int tC = (p + 2 < end) ? __ldg(&g_perm_o[p + 2]) : tB;
        int s_n = s; float lv_n = lv;
        if (p + 1 < end) {
            s_n = __ldg(&s_idx[tB]);
            lv_n = (lane < 16) ? __ldg(&g_lat1[(size_t)tB * 16 + lane]) : 0.f;
        }
        float acc = 0.f;
#pragma unroll
        for (int k = 0; k < 16; k++)
            acc += __shfl_sync(0xffffffffu, lv, k) * wk[k];
        red1(&g_h[s * 32 + lane], acc);
        s = s_n; lv = lv_n; tB = tC;
    }
}

// -------- layer-2 spmm + k=0 reduction, relu(h+bias1) applied on read -----
// blocks [0, NBS): warp per s, k>=1 red4 into h2
// blocks [NBS, NBS+512): grid-stride k=0 reduction into h2 row 0
#define NBS ((Nn + 7) / 8)
__global__ void __launch_bounds__(256)
k_spmm2h(const int* __restrict__ o_idx, const float* __restrict__ bias1) {
    __shared__ __align__(16) float stage[8][16 * 32];
    int wid = threadIdx.x >> 5, lane = threadIdx.x & 31;
    float b1v = __ldg(&bias1[lane]);

    if (blockIdx.x >= NBS) {
        // ---- k=0 bin: block-aggregated global reduction ----
        int gw = (blockIdx.x - NBS) * 8 + wid;
        int nw = 512 * 8;
        float acc = 0.f;
        for (int t = gw; t < NTt; t += nw) {
            float l0 = __ldg(&g_lat2[(size_t)t * 16]);
            int o = __ldg(&o_idx[t]);
            acc += l0 * fmaxf(g_h[o * 32 + lane] + b1v, 0.f);
        }
        stage[wid][lane] = acc;
        __syncthreads();
        if (wid == 0) {
            float tot = 0.f;
#pragma unroll
            for (int i = 0; i < 8; i++) tot += stage[i][lane];
            red1(&g_h2[lane], tot);
        }
        return;
    }

    int s = blockIdx.x * 8 + wid;
    if (s >= Nn) return;
    int deg = g_deg_s[s];
    if (deg == 0) return;
    int beg = g_off_s[s], end = beg + deg;
    float acc[16];
#pragma unroll
    for (int k = 0; k < 16; k++) acc[k] = 0.f;

    int tA = __ldg(&g_perm_s[beg]);
    int tB = (beg + 1 < end) ? __ldg(&g_perm_s[beg + 1]) : tA;
    int o = __ldg(&o_idx[tA]);
    float lv = (lane < 16) ? __ldg(&g_lat2[(size_t)tA * 16 + lane]) : 0.f;
    for (int p = beg; p < end; p++) {
        int tC = (p + 2 < end) ? __ldg(&g_perm_s[p + 2]) : tB;
        int o_n = o; float lv_n = lv;
        if (p + 1 < end) {
            o_n = __ldg(&o_idx[tB]);
            lv_n = (lane < 16) ? __ldg(&g_lat2[(size_t)tB * 16 + lane]) : 0.f;
        }
        float hv = fmaxf(g_h[o * 32 + lane] + b1v, 0.f);
#pragma unroll
        for (int k = 1; k < 16; k++)
            acc[k] += __shfl_sync(0xffffffffu, lv, k) * hv;
        o = o_n; lv = lv_n; tB = tC;
    }
    float* st = stage[wid];
#pragma unroll
    for (int k = 1; k < 16; k++) st[k * 32 + lane] = acc[k];
    __syncwarp();
#pragma unroll
    for (int it = 0; it < 4; it++) {
        int idx = it * 32 + lane;        // 0..127 over 16 rows x 8 float4
        if (idx >= 8) {                  // skip k=0 (handled by k=0 blocks)
            int k = idx >> 3, q = idx & 7;
            float4 v = ((float4*)st)[idx];
            int j = s * k;
            red4(&((float4*)g_h2)[(size_t)j * 8 + q], v);
        }
    }
}

// ------------------- einsum + bias2: out, 2 nodes / thread ----------------
__global__ void __launch_bounds__(256)
k_out(const float* __restrict__ w2, const float* __restrict__ bias2,
      float* __restrict__ out) {
    extern __shared__ __align__(16) float sw2[];   // 16*32*32 floats = 64 KB
    for (int i = threadIdx.x; i < 16 * 32 * 32; i += 256) sw2[i] = w2[i];
    __syncthreads();
    int n0 = blockIdx.x * 256 + threadIdx.x;       // 0..24999
    if (n0 >= Nn / 2) return;
    int n1 = n0 + Nn / 2;
    ULL accA[16], accB[16];
#pragma unroll
    for (int c2 = 0; c2 < 16; c2++) {
        accA[c2] = ((const ULL*)bias2)[c2];
        accB[c2] = accA[c2];
    }
#pragma unroll 1
    for (int r = 0; r < 16; r++) {
        int jA = r * Nn + n0;
        int jB = jA + Nn / 2;
        float ra = g_rowsum[jA], rb = g_rowsum[jB];
        float invA = (ra > 0.f) ? __frcp_rn(ra) : 0.f;
        float invB = (rb > 0.f) ? __frcp_rn(rb) : 0.f;
        const float4* hA = (const float4*)&g_h2[(size_t)jA * 32];
        const float4* hB = (const float4*)&g_h2[(size_t)jB * 32];
#pragma unroll
        for (int e4 = 0; e4 < 8; e4++) {
            float4 va = hA[e4];
            float4 vb = hB[e4];
            float xa[4] = { va.x * invA, va.y * invA, va.z * invA, va.w * invA };
            float xb[4] = { vb.x * invB, vb.y * invB, vb.z * invB, vb.w * invB };
#pragma unroll
            for (int u = 0; u < 4; u++) {
                int e = e4 * 4 + u;
                ULL sa = splat2(xa[u]);
                ULL sb = splat2(xb[u]);
                const float4* wr4 = (const float4*)&sw2[(r * 32 + e) * 32];
#pragma unroll
                for (int c4 = 0; c4 < 8; c4++) {
                    F4U w; w.f = wr4[c4];
                    accA[2 * c4]     = ffma2(sa, w.u[0], accA[2 * c4]);
                    accA[2 * c4 + 1] = ffma2(sa, w.u[1], accA[2 * c4 + 1]);
                    accB[2 * c4]     = ffma2(sb, w.u[0], accB[2 * c4]);
                    accB[2 * c4 + 1] = ffma2(sb, w.u[1], accB[2 * c4 + 1]);
                }
            }
        }
    }
    ULL* opA = (ULL*)(out + (size_t)n0 * 32);
    ULL* opB = (ULL*)(out + (size_t)n1 * 32);
#pragma unroll
    for (int c2 = 0; c2 < 16; c2++) { opA[c2] = accA[c2]; opB[c2] = accB[c2]; }
}

// ------------------------- launch -----------------------------------------
extern "C" void kernel_launch(void* const* d_in, const int* in_sizes, int n_in,
                              void* d_out, int out_size) {
    const int*   s_idx = (const int*)d_in[0];
    const int*   o_idx = (const int*)d_in[1];
    const float* nhots = (const float*)d_in[2];
    const float* W1a   = (const float*)d_in[3];
    const float* b1a   = (const float*)d_in[4];
    const float* W1b   = (const float*)d_in[5];
    const float* b1b   = (const float*)d_in[6];
    const float* W2a   = (const float*)d_in[7];
    const float* b2a   = (const float*)d_in[8];
    const float* W2b   = (const float*)d_in[9];
    const float* b2b   = (const float*)d_in[10];
    const float* w1    = (const float*)d_in[11];
    const float* w2    = (const float*)d_in[12];
    const float* bias1 = (const float*)d_in[13];
    const float* bias2 = (const float*)d_in[14];
    float* out = (float*)d_out;

    static float* lat1p = nullptr;
    static float* lat2p = nullptr;
    static float* colp = nullptr;
    static float* rowp = nullptr;
    static cudaStream_t s1 = nullptr;
    static cudaEvent_t evF = nullptr, evS = nullptr, evH = nullptr;
    if (!lat1p) {
        cudaGetSymbolAddress((void**)&lat1p, g_lat1);
        cudaGetSymbolAddress((void**)&lat2p, g_lat2);
        cudaGetSymbolAddress((void**)&colp, g_colsum);
        cudaGetSymbolAddress((void**)&rowp, g_rowsum);
        cudaFuncSetAttribute(k_mlp, cudaFuncAttributeMaxDynamicSharedMemorySize,
                             SM_FLOATS * (int)sizeof(float));
        cudaFuncSetAttribute(k_out, cudaFuncAttributeMaxDynamicSharedMemorySize,
                             16 * 32 * 32 * (int)sizeof(float));
        cudaStreamCreateWithFlags(&s1, cudaStreamNonBlocking);
        cudaEventCreateWithFlags(&evF, cudaEventDisableTiming);
        cudaEventCreateWithFlags(&evS, cudaEventDisableTiming);
        cudaEventCreateWithFlags(&evH, cudaEventDisableTiming);
    }

    int mlp_blocks = (NTt + 127) / 128;
    size_t mlp_smem = SM_FLOATS * sizeof(float);

    k_init_small<<<512, 256>>>();                              // 0
    cudaEventRecord(evF, 0);                                   // fork point

    // side stream: CSR build + h2 zero, concurrent with k_mlp
    cudaStreamWaitEvent(s1, evF, 0);
    k_deg<<<(NTt + 255) / 256, 256, 0, s1>>>(s_idx, o_idx);
    k_alloc<<<(Nn + 255) / 256, 256, 0, s1>>>();
    k_scatter<<<(NTt + 255) / 256, 256, 0, s1>>>(s_idx, o_idx);
    cudaEventRecord(evS, s1);
    k_init_h2<<<2048, 256, 0, s1>>>();
    cudaEventRecord(evH, s1);

    // main stream: MLP -> spmm1 -> spmm2(+relu) -> out
    k_mlp<<<mlp_blocks, 256, mlp_smem>>>(s_idx, o_idx, nhots,
                                         W1a, b1a, W1b, b1b,
                                         W2a, b2a, W2b, b2b,
                                         lat1p, lat2p, colp, rowp);
    cudaStreamWaitEvent(0, evS, 0);                            // join CSR build
    k_spmm1<<<(Nn * 32 + 255) / 256, 256>>>(s_idx, w1);
    cudaStreamWaitEvent(0, evH, 0);                            // join h2-zero
    k_spmm2h<<<NBS + 512, 256>>>(o_idx, bias1);
    k_out<<<(Nn / 2 + 255) / 256, 256, 16 * 32 * 32 * (int)sizeof(float)>>>(w2, bias2, out);
}